// round 12
// baseline (speedup 1.0000x reference)
#include <cuda_runtime.h>
#include <cuda_bf16.h>
#include <cstdint>
#include <math.h>

// Problem constants
#define B_  2
#define S_  4096
#define D_  1024
#define H_  16
#define HD_ 64
#define M_  512
#define L_  1024
#define HID_ 2816
#define NSTEP 8

// ---------------------------------------------------------------------------
// Scratch (device globals; no allocation allowed)
// ---------------------------------------------------------------------------
__device__ float g_allout[B_ * S_ * D_];
__device__ float g_qx[B_ * S_ * D_];
__device__ float g_kx[B_ * S_ * D_];
__device__ float g_vx[B_ * S_ * D_];
__device__ float g_a  [B_ * M_ * D_];
__device__ float g_hn [B_ * M_ * D_];
__device__ float g_t1 [B_ * M_ * HID_];
__device__ float g_t3 [B_ * M_ * HID_];
__device__ float g_m2 [B_ * M_ * D_];
__device__ float g_k  [B_ * M_ * D_];
__device__ float g_v  [B_ * M_ * D_];

// Pre-split, pre-transposed weights: [n][k] bf16 hi/lo planes
#define OFF_WM  0LL
#define OFF_WKM 1048576LL
#define OFF_WVM 2097152LL
#define OFF_WQ  3145728LL
#define OFF_WK  4194304LL
#define OFF_WV  5242880LL
#define OFF_WO  6291456LL
#define OFF_W1  7340032LL
#define OFF_W3  10223616LL
#define OFF_W2  13107200LL
#define WT_ELEMS 15990784LL
__device__ __nv_bfloat16 g_wth[WT_ELEMS];
__device__ __nv_bfloat16 g_wtl[WT_ELEMS];

// ---------------------------------------------------------------------------
// Warp-level bf16 MMA + ldmatrix helpers (valid under compute_103 target)
// ---------------------------------------------------------------------------
__device__ __forceinline__ void mma16816(float* c,
                                         uint32_t a0, uint32_t a1, uint32_t a2, uint32_t a3,
                                         uint32_t b0, uint32_t b1)
{
    asm volatile(
        "mma.sync.aligned.m16n8k16.row.col.f32.bf16.bf16.f32 "
        "{%0,%1,%2,%3}, {%4,%5,%6,%7}, {%8,%9}, {%0,%1,%2,%3};"
        : "+f"(c[0]), "+f"(c[1]), "+f"(c[2]), "+f"(c[3])
        : "r"(a0), "r"(a1), "r"(a2), "r"(a3), "r"(b0), "r"(b1));
}

__device__ __forceinline__ void ldsm4(uint32_t& r0, uint32_t& r1,
                                      uint32_t& r2, uint32_t& r3, uint32_t addr)
{
    asm volatile("ldmatrix.sync.aligned.m8n8.x4.shared.b16 {%0,%1,%2,%3}, [%4];"
        : "=r"(r0), "=r"(r1), "=r"(r2), "=r"(r3) : "r"(addr));
}

__device__ __forceinline__ uint32_t smem_u32(const void* p) {
    uint32_t a;
    asm("{ .reg .u64 t; cvta.to.shared.u64 t, %1; cvt.u32.u64 %0, t; }"
        : "=r"(a) : "l"(p));
    return a;
}

// ---------------------------------------------------------------------------
// Weight prep: W (K x N fp32, row-major) -> Wh/Wl (N x K bf16, row-major)
// ---------------------------------------------------------------------------
__global__ __launch_bounds__(256)
void prep_weight_kernel(const float* __restrict__ W,
                        __nv_bfloat16* __restrict__ Wh,
                        __nv_bfloat16* __restrict__ Wl,
                        int K, int N)
{
    __shared__ float t[32][33];
    const int n0 = blockIdx.x * 32, k0 = blockIdx.y * 32;
    const int tx = threadIdx.x, ty = threadIdx.y;
    #pragma unroll
    for (int i = 0; i < 4; i++)
        t[ty + i * 8][tx] = W[(size_t)(k0 + ty + i * 8) * N + n0 + tx];
    __syncthreads();
    #pragma unroll
    for (int i = 0; i < 4; i++) {
        int n = n0 + ty + i * 8, k = k0 + tx;
        float v = t[tx][ty + i * 8];
        __nv_bfloat16 h = __float2bfloat16(v);
        Wh[(size_t)n * K + k] = h;
        Wl[(size_t)n * K + k] = __float2bfloat16(v - __bfloat162float(h));
    }
}

// ---------------------------------------------------------------------------
// Split-bf16 GEMM, pre-transposed bf16 B planes.
// C[z][mat] = A[z] (rows x K fp32) @ Bt[mat]^T  (Bt is N x K bf16 hi/lo)
// acc = Ah*Bh + Ah*Bl + Al*Bh. Optional SwiGLU gate on A (A = silu(A)*A3).
// Tile TM x TN, BK=32, 256 threads (2M x 4N warps).
// ---------------------------------------------------------------------------
#define BK 32
#define AST 40
#define ASTB (AST * 2)

template <int TM, int TN, bool ACC, bool GATE>
__global__ __launch_bounds__(256, 2)
void mma_gemm_kernel(const float* __restrict__ A, const float* __restrict__ A3,
                     long long aBatch,
                     const __nv_bfloat16* __restrict__ Bh0,
                     const __nv_bfloat16* __restrict__ Bh1,
                     const __nv_bfloat16* __restrict__ Bh2,
                     const __nv_bfloat16* __restrict__ Bl0,
                     const __nv_bfloat16* __restrict__ Bl1,
                     const __nv_bfloat16* __restrict__ Bl2,
                     float* __restrict__ C0, float* __restrict__ C1, float* __restrict__ C2,
                     long long cB0, long long cB1, long long cB2,
                     int K, int N, int tilesN)
{
    constexpr int WM = TM / 2;
    constexpr int WN = TN / 4;
    constexpr int MT = WM / 16;
    constexpr int NT = WN / 8;
    constexpr int P  = NT / 2;
    constexpr int A_HALF = TM * AST * 2;
    constexpr int B_HALF = TN * AST * 2;
    constexpr int CA  = TM / 32;        // A float4 loads per thread
    constexpr int TPR = 256 / TM;       // threads per A row
    constexpr int TPRB = 256 / TN;      // threads per B row
    constexpr int EB  = 32 / TPRB;      // bf16 elems per thread per plane
    constexpr int V4  = EB / 8;         // uint4 loads per plane

    extern __shared__ char smem[];
    __nv_bfloat16* Ahi = (__nv_bfloat16*)smem;
    __nv_bfloat16* Alo = (__nv_bfloat16*)(smem + A_HALF);
    __nv_bfloat16* Bhi = (__nv_bfloat16*)(smem + 2 * A_HALF);
    __nv_bfloat16* Blo = (__nv_bfloat16*)(smem + 2 * A_HALF + B_HALF);

    const int tid = threadIdx.x;
    const int wid = tid >> 5, lane = tid & 31;
    const int wm = wid & 1, wn = wid >> 1;
    const int r  = lane >> 2, qc = (lane & 3) * 2;

    const int tn  = blockIdx.x % tilesN;
    const int mat = blockIdx.x / tilesN;
    const int bz  = blockIdx.z;
    const int m0  = blockIdx.y * TM;
    const int n0  = tn * TN;

    const __nv_bfloat16* Bth = (mat == 0) ? Bh0 : ((mat == 1) ? Bh1 : Bh2);
    const __nv_bfloat16* Btl = (mat == 0) ? Bl0 : ((mat == 1) ? Bl1 : Bl2);
    float*       Cm = (mat == 0) ? C0 : ((mat == 1) ? C1 : C2);
    const long long cB = (mat == 0) ? cB0 : ((mat == 1) ? cB1 : cB2);

    const float* Ab  = A + (long long)bz * aBatch + (long long)m0 * K;
    const float* A3b = GATE ? (A3 + (long long)bz * aBatch + (long long)m0 * K) : nullptr;

    const uint32_t sAhi = smem_u32(Ahi);
    const uint32_t sBhi = smem_u32(Bhi);
    const uint32_t aLaneOff = (uint32_t)((lane & 15) * AST + (lane >> 4) * 8) * 2;
    const uint32_t bLaneOff = (uint32_t)((((lane & 7) + ((lane >> 4) << 3)) * AST
                                          + ((lane >> 3) & 1) * 8) * 2);

    const int ar  = tid / TPR,  akb = (tid % TPR) * (32 / TPR);
    const int brow = tid / TPRB, bkp = tid % TPRB;

    const __nv_bfloat16* Bph = Bth + (size_t)(n0 + brow) * K + bkp * EB;
    const __nv_bfloat16* Bpl = Btl + (size_t)(n0 + brow) * K + bkp * EB;

    float4 pa[CA], pa3[GATE ? CA : 1];
    uint4  pbh[V4], pbl[V4];
    {
        const float* Ap = Ab + (size_t)ar * K + akb;
        #pragma unroll
        for (int j = 0; j < CA; j++) pa[j] = *(const float4*)(Ap + j * 4);
        if (GATE) {
            const float* A3p = A3b + (size_t)ar * K + akb;
            #pragma unroll
            for (int j = 0; j < CA; j++) pa3[j] = *(const float4*)(A3p + j * 4);
        }
        #pragma unroll
        for (int v = 0; v < V4; v++) {
            pbh[v] = *(const uint4*)(Bph + v * 8);
            pbl[v] = *(const uint4*)(Bpl + v * 8);
        }
    }

    float acc[MT][NT][4];
    #pragma unroll
    for (int i = 0; i < MT; i++)
        #pragma unroll
        for (int j = 0; j < NT; j++)
            #pragma unroll
            for (int e = 0; e < 4; e++) acc[i][j][e] = 0.f;

    const int NC = K / BK;
    #pragma unroll 1
    for (int kc = 0; kc < NC; kc++) {
        // ---- A: (gate) + convert + split-store ----
        #pragma unroll
        for (int j = 0; j < CA; j++) {
            float4 v = pa[j];
            if (GATE) {
                float4 g = pa3[j];
                v.x = (v.x / (1.f + __expf(-v.x))) * g.x;
                v.y = (v.y / (1.f + __expf(-v.y))) * g.y;
                v.z = (v.z / (1.f + __expf(-v.z))) * g.z;
                v.w = (v.w / (1.f + __expf(-v.w))) * g.w;
            }
            __nv_bfloat16 h0 = __float2bfloat16(v.x);
            __nv_bfloat16 h1 = __float2bfloat16(v.y);
            __nv_bfloat16 h2 = __float2bfloat16(v.z);
            __nv_bfloat16 h3 = __float2bfloat16(v.w);
            __nv_bfloat162 hp0 = __halves2bfloat162(h0, h1);
            __nv_bfloat162 hp1 = __halves2bfloat162(h2, h3);
            __nv_bfloat162 lp0 = __floats2bfloat162_rn(v.x - __bfloat162float(h0),
                                                       v.y - __bfloat162float(h1));
            __nv_bfloat162 lp1 = __floats2bfloat162_rn(v.z - __bfloat162float(h2),
                                                       v.w - __bfloat162float(h3));
            int off = ar * AST + akb + j * 4;
            *(uint2*)&Ahi[off] = make_uint2(*(uint32_t*)&hp0, *(uint32_t*)&hp1);
            *(uint2*)&Alo[off] = make_uint2(*(uint32_t*)&lp0, *(uint32_t*)&lp1);
        }
        // ---- B: direct vector copy of pre-split planes ----
        #pragma unroll
        for (int v = 0; v < V4; v++) {
            int off = brow * AST + bkp * EB + v * 8;
            *(uint2*)&Bhi[off]     = make_uint2(pbh[v].x, pbh[v].y);
            *(uint2*)&Bhi[off + 4] = make_uint2(pbh[v].z, pbh[v].w);
            *(uint2*)&Blo[off]     = make_uint2(pbl[v].x, pbl[v].y);
            *(uint2*)&Blo[off + 4] = make_uint2(pbl[v].z, pbl[v].w);
        }
        __syncthreads();

        // ---- prefetch next chunk ----
        if (kc + 1 < NC) {
            const int k0n = (kc + 1) * BK;
            const float* Ap = Ab + (size_t)ar * K + k0n + akb;
            #pragma unroll
            for (int j = 0; j < CA; j++) pa[j] = *(const float4*)(Ap + j * 4);
            if (GATE) {
                const float* A3p = A3b + (size_t)ar * K + k0n + akb;
                #pragma unroll
                for (int j = 0; j < CA; j++) pa3[j] = *(const float4*)(A3p + j * 4);
            }
            #pragma unroll
            for (int v = 0; v < V4; v++) {
                pbh[v] = *(const uint4*)(Bph + k0n + v * 8);
                pbl[v] = *(const uint4*)(Bpl + k0n + v * 8);
            }
        }

        // ---- MMA: 2 k-steps of 16, fragments via ldmatrix ----
        #pragma unroll
        for (int ks = 0; ks < 2; ks++) {
            const uint32_t kOff = ks * 32;
            uint32_t bh[P][4], bl[P][4];
            #pragma unroll
            for (int p = 0; p < P; p++) {
                uint32_t baddr = sBhi + (uint32_t)(wn * WN + p * 16) * ASTB + kOff + bLaneOff;
                ldsm4(bh[p][0], bh[p][1], bh[p][2], bh[p][3], baddr);
                ldsm4(bl[p][0], bl[p][1], bl[p][2], bl[p][3], baddr + B_HALF);
            }
            #pragma unroll
            for (int mt = 0; mt < MT; mt++) {
                uint32_t aaddr = sAhi + (uint32_t)(wm * WM + mt * 16) * ASTB + kOff + aLaneOff;
                uint32_t ah0, ah1, ah2, ah3, al0, al1, al2, al3;
                ldsm4(ah0, ah1, ah2, ah3, aaddr);
                ldsm4(al0, al1, al2, al3, aaddr + A_HALF);
                #pragma unroll
                for (int nt = 0; nt < NT; nt++) {
                    uint32_t b0 = bh[nt >> 1][(nt & 1) * 2];
                    uint32_t b1 = bh[nt >> 1][(nt & 1) * 2 + 1];
                    uint32_t c0 = bl[nt >> 1][(nt & 1) * 2];
                    uint32_t c1 = bl[nt >> 1][(nt & 1) * 2 + 1];
                    mma16816(acc[mt][nt], ah0, ah1, ah2, ah3, b0, b1);
                    mma16816(acc[mt][nt], ah0, ah1, ah2, ah3, c0, c1);
                    mma16816(acc[mt][nt], al0, al1, al2, al3, b0, b1);
                }
            }
        }
        __syncthreads();
    }

    // ---- epilogue ----
    float* Cb = Cm + (long long)bz * cB;
    #pragma unroll
    for (int mt = 0; mt < MT; mt++) {
        int row0 = m0 + wm * WM + mt * 16 + r;
        #pragma unroll
        for (int nt = 0; nt < NT; nt++) {
            int col = n0 + wn * WN + nt * 8 + qc;
            float* p0 = Cb + (size_t)row0 * N + col;
            float* p1 = Cb + (size_t)(row0 + 8) * N + col;
            float2 v0 = make_float2(acc[mt][nt][0], acc[mt][nt][1]);
            float2 v1 = make_float2(acc[mt][nt][2], acc[mt][nt][3]);
            if (ACC) {
                float2 o0 = *(const float2*)p0;
                float2 o1 = *(const float2*)p1;
                v0.x += o0.x; v0.y += o0.y;
                v1.x += o1.x; v1.y += o1.y;
            }
            *(float2*)p0 = v0;
            *(float2*)p1 = v1;
        }
    }
}

#define SMEM_OF(TM, TN) (2 * (TM) * AST * 2 + 2 * (TN) * AST * 2)

// ---------------------------------------------------------------------------
// RMSNorm
// ---------------------------------------------------------------------------
__global__ __launch_bounds__(256)
void rmsnorm_kernel(const float* __restrict__ x, const float* __restrict__ w,
                    float* __restrict__ o)
{
    const int row = blockIdx.x;
    const int tid = threadIdx.x;
    const float4 v = *(const float4*)(x + (size_t)row * D_ + tid * 4);
    float ss = v.x * v.x + v.y * v.y + v.z * v.z + v.w * v.w;
    #pragma unroll
    for (int off = 16; off; off >>= 1)
        ss += __shfl_xor_sync(0xffffffffu, ss, off);
    __shared__ float ws[8];
    __shared__ float s_inv;
    if ((tid & 31) == 0) ws[tid >> 5] = ss;
    __syncthreads();
    if (tid == 0) {
        float t = 0.f;
        #pragma unroll
        for (int i = 0; i < 8; i++) t += ws[i];
        s_inv = rsqrtf(t * (1.0f / D_) + 1e-5f);
    }
    __syncthreads();
    const float inv = s_inv;
    const float4 wv = *(const float4*)(w + tid * 4);
    float4 ov;
    ov.x = v.x * inv * wv.x;
    ov.y = v.y * inv * wv.y;
    ov.z = v.z * inv * wv.z;
    ov.w = v.w * inv * wv.w;
    *(float4*)(o + (size_t)row * D_ + tid * 4) = ov;
}

// ---------------------------------------------------------------------------
// RoPE: rows of width 1024; position = posOff + (row % rowsMod)
// ---------------------------------------------------------------------------
__global__ void rope_kernel(float* __restrict__ t,
                            const float* __restrict__ cosT,
                            const float* __restrict__ sinT,
                            int rowsMod, int posOff, int nPairs)
{
    int id = blockIdx.x * blockDim.x + threadIdx.x;
    if (id >= nPairs) return;
    int pair = id & 511;
    int row  = id >> 9;
    int pos  = posOff + (row % rowsMod);
    int i    = pair & 31;
    float c = cosT[pos * 32 + i];
    float s = sinT[pos * 32 + i];
    float2* p = (float2*)(t + (size_t)row * D_ + pair * 2);
    float2 v = *p;
    float2 o;
    o.x = v.x * c - v.y * s;
    o.y = v.x * s + v.y * c;
    *p = o;
}

// ---------------------------------------------------------------------------
// Flash-style causal attention (x-part queries only).
// ---------------------------------------------------------------------------
#define ALD 65
#define ATTN_SMEM ((4 * 64 * ALD + 3 * 64) * (int)sizeof(float))

__global__ __launch_bounds__(256)
void attn_kernel(const float* __restrict__ Qx,
                 const float* __restrict__ Km, const float* __restrict__ Vm,
                 const float* __restrict__ Kx, const float* __restrict__ Vx,
                 float* __restrict__ Out, int sBase)
{
    extern __shared__ float sm[];
    float* Qs   = sm;
    float* Ks   = Qs + 64 * ALD;
    float* Vs   = Ks + 64 * ALD;
    float* Ss   = Vs + 64 * ALD;
    float* mrow = Ss + 64 * ALD;
    float* lrow = mrow + 64;
    float* crow = lrow + 64;

    const int b  = blockIdx.z;
    const int h  = blockIdx.y;
    const int qt = blockIdx.x;
    const int tid = threadIdx.x;
    const int tx = tid & 15, ty = tid >> 4;
    const int q0 = qt * 64;
    const float scale = 0.125f;

    for (int e = tid; e < 64 * 16; e += 256) {
        int i = e >> 4, d4 = (e & 15) * 4;
        float4 v = *(const float4*)&Qx[((size_t)(b * S_ + sBase + q0 + i)) * D_ + h * HD_ + d4];
        Qs[i * ALD + d4 + 0] = v.x;
        Qs[i * ALD + d4 + 1] = v.y;
        Qs[i * ALD + d4 + 2] = v.z;
        Qs[i * ALD + d4 + 3] = v.w;
    }
    if (tid < 64) { mrow[tid] = -1e30f; lrow[tid] = 0.f; }
    float acc[4][4];
    #pragma unroll
    for (int i = 0; i < 4; i++)
        #pragma unroll
        for (int j = 0; j < 4; j++) acc[i][j] = 0.f;
    __syncthreads();

    const int nkt = qt + 9;
    for (int kt = 0; kt < nkt; kt++) {
        const float* Kp;
        const float* Vp;
        size_t rb;
        if (kt < 8) {
            Kp = Km; Vp = Vm;
            rb = (size_t)(b * M_ + kt * 64);
        } else {
            Kp = Kx; Vp = Vx;
            rb = (size_t)(b * S_ + sBase + (kt - 8) * 64);
        }
        for (int e = tid; e < 64 * 16; e += 256) {
            int j = e >> 4, d4 = (e & 15) * 4;
            size_t base = (rb + j) * D_ + h * HD_ + d4;
            float4 kv = *(const float4*)&Kp[base];
            Ks[j * ALD + d4 + 0] = kv.x;
            Ks[j * ALD + d4 + 1] = kv.y;
            Ks[j * ALD + d4 + 2] = kv.z;
            Ks[j * ALD + d4 + 3] = kv.w;
            float4 vv = *(const float4*)&Vp[base];
            Vs[j * ALD + d4 + 0] = vv.x;
            Vs[j * ALD + d4 + 1] = vv.y;
            Vs[j * ALD + d4 + 2] = vv.z;
            Vs[j * ALD + d4 + 3] = vv.w;
        }
        __syncthreads();

        float s4[4][4];
        #pragma unroll
        for (int i = 0; i < 4; i++)
            #pragma unroll
            for (int j = 0; j < 4; j++) s4[i][j] = 0.f;
        for (int d = 0; d < 64; d++) {
            float rq[4], rk[4];
            #pragma unroll
            for (int ii = 0; ii < 4; ii++) rq[ii] = Qs[(ty * 4 + ii) * ALD + d];
            #pragma unroll
            for (int jj = 0; jj < 4; jj++) rk[jj] = Ks[(tx * 4 + jj) * ALD + d];
            #pragma unroll
            for (int ii = 0; ii < 4; ii++)
                #pragma unroll
                for (int jj = 0; jj < 4; jj++)
                    s4[ii][jj] = fmaf(rq[ii], rk[jj], s4[ii][jj]);
        }
        const int qg0 = M_ + q0;
        #pragma unroll
        for (int ii = 0; ii < 4; ii++) {
            int qi = qg0 + ty * 4 + ii;
            #pragma unroll
            for (int jj = 0; jj < 4; jj++) {
                int kj = kt * 64 + tx * 4 + jj;
                float val = (kj <= qi) ? s4[ii][jj] * scale : -1e30f;
                Ss[(ty * 4 + ii) * ALD + tx * 4 + jj] = val;
            }
        }
        __syncthreads();

        if (tid < 64) {
            float mold = mrow[tid];
            float mx = mold;
            for (int j = 0; j < 64; j++) mx = fmaxf(mx, Ss[tid * ALD + j]);
            float c = __expf(mold - mx);
            float sum = 0.f;
            for (int j = 0; j < 64; j++) {
                float p = __expf(Ss[tid * ALD + j] - mx);
                Ss[tid * ALD + j] = p;
                sum += p;
            }
            mrow[tid] = mx;
            lrow[tid] = lrow[tid] * c + sum;
            crow[tid] = c;
        }
        __syncthreads();

        float cc[4];
        #pragma unroll
        for (int ii = 0; ii < 4; ii++) cc[ii] = crow[ty * 4 + ii];
        #pragma unroll
        for (int ii = 0; ii < 4; ii++)
            #pragma unroll
            for (int dd = 0; dd < 4; dd++) acc[ii][dd] *= cc[ii];
        for (int j = 0; j < 64; j++) {
            float rp[4], rv[4];
            #pragma unroll
            for (int ii = 0; ii < 4; ii++) rp[ii] = Ss[(ty * 4 + ii) * ALD + j];
            #pragma unroll
            for (int dd = 0; dd < 4; dd++) rv[dd] = Vs[j * ALD + tx * 4 + dd];
            #pragma unroll
            for (int ii = 0; ii < 4; ii++)
                #pragma unroll
                for (int dd = 0; dd < 4; dd++)
                    acc[ii][dd] = fmaf(rp[ii], rv[dd], acc[ii][dd]);
        }
        __syncthreads();
    }

    if (tid < 64) crow[tid] = 1.f / lrow[tid];
    __syncthreads();
    #pragma unroll
    for (int ii = 0; ii < 4; ii++) {
        float inv = crow[ty * 4 + ii];
        int grow = b * S_ + sBase + q0 + ty * 4 + ii;
        float4 o;
        o.x = acc[ii][0] * inv;
        o.y = acc[ii][1] * inv;
        o.z = acc[ii][2] * inv;
        o.w = acc[ii][3] * inv;
        *(float4*)&Out[(size_t)grow * D_ + h * HD_ + tx * 4] = o;
    }
}

// ---------------------------------------------------------------------------
// Launch
// ---------------------------------------------------------------------------
extern "C" void kernel_launch(void* const* d_in, const int* in_sizes, int n_in,
                              void* d_out, int out_size)
{
    const float* x        = (const float*)d_in[0];
    const float* cosT     = (const float*)d_in[1];
    const float* sinT     = (const float*)d_in[2];
    const float* wq       = (const float*)d_in[3];
    const float* wk       = (const float*)d_in[4];
    const float* wv       = (const float*)d_in[5];
    const float* wo       = (const float*)d_in[6];
    const float* wm       = (const float*)d_in[7];
    const float* wkm      = (const float*)d_in[8];
    const float* wvm      = (const float*)d_in[9];
    const float* w1       = (const float*)d_in[10];
    const float* w3       = (const float*)d_in[11];
    const float* w2       = (const float*)d_in[12];
    const float* ffn_nw   = (const float*)d_in[13];
    const float* mem_nw   = (const float*)d_in[14];
    const float* omem     = (const float*)d_in[15];
    float* out = (float*)d_out;

    float *p_allout, *p_qx, *p_kx, *p_vx, *p_a, *p_hn, *p_t1, *p_t3, *p_m2, *p_k, *p_v;
    __nv_bfloat16 *wth, *wtl;
    cudaGetSymbolAddress((void**)&p_allout, g_allout);
    cudaGetSymbolAddress((void**)&p_qx, g_qx);
    cudaGetSymbolAddress((void**)&p_kx, g_kx);
    cudaGetSymbolAddress((void**)&p_vx, g_vx);
    cudaGetSymbolAddress((void**)&p_a,  g_a);
    cudaGetSymbolAddress((void**)&p_hn, g_hn);
    cudaGetSymbolAddress((void**)&p_t1, g_t1);
    cudaGetSymbolAddress((void**)&p_t3, g_t3);
    cudaGetSymbolAddress((void**)&p_m2, g_m2);
    cudaGetSymbolAddress((void**)&p_k,  g_k);
    cudaGetSymbolAddress((void**)&p_v,  g_v);
    cudaGetSymbolAddress((void**)&wth,  g_wth);
    cudaGetSymbolAddress((void**)&wtl,  g_wtl);

    cudaFuncSetAttribute(attn_kernel,
                         cudaFuncAttributeMaxDynamicSharedMemorySize, ATTN_SMEM);
    cudaFuncSetAttribute(mma_gemm_kernel<128, 128, false, false>,
                         cudaFuncAttributeMaxDynamicSharedMemorySize, SMEM_OF(128, 128));
    cudaFuncSetAttribute(mma_gemm_kernel<64, 64, false, false>,
                         cudaFuncAttributeMaxDynamicSharedMemorySize, SMEM_OF(64, 64));
    cudaFuncSetAttribute(mma_gemm_kernel<64, 128, false, false>,
                         cudaFuncAttributeMaxDynamicSharedMemorySize, SMEM_OF(64, 128));
    cudaFuncSetAttribute(mma_gemm_kernel<64, 64, true, true>,
                         cudaFuncAttributeMaxDynamicSharedMemorySize, SMEM_OF(64, 64));

    const long long MD  = (long long)M_ * D_;
    const long long MH  = (long long)M_ * HID_;
    const long long SD  = (long long)S_ * D_;

    // ---- Prep: split + transpose all weights into bf16 hi/lo planes ----
    {
        dim3 blk(32, 8);
        prep_weight_kernel<<<dim3(32, 32), blk>>>(wm,  wth + OFF_WM,  wtl + OFF_WM,  D_, D_);
        prep_weight_kernel<<<dim3(32, 32), blk>>>(wkm, wth + OFF_WKM, wtl + OFF_WKM, D_, D_);
        prep_weight_kernel<<<dim3(32, 32), blk>>>(wvm, wth + OFF_WVM, wtl + OFF_WVM, D_, D_);
        prep_weight_kernel<<<dim3(32, 32), blk>>>(wq,  wth + OFF_WQ,  wtl + OFF_WQ,  D_, D_);
        prep_weight_kernel<<<dim3(32, 32), blk>>>(wk,  wth + OFF_WK,  wtl + OFF_WK,  D_, D_);
        prep_weight_kernel<<<dim3(32, 32), blk>>>(wv,  wth + OFF_WV,  wtl + OFF_WV,  D_, D_);
        prep_weight_kernel<<<dim3(32, 32), blk>>>(wo,  wth + OFF_WO,  wtl + OFF_WO,  D_, D_);
        prep_weight_kernel<<<dim3(88, 32), blk>>>(w1,  wth + OFF_W1,  wtl + OFF_W1,  D_, HID_);
        prep_weight_kernel<<<dim3(88, 32), blk>>>(w3,  wth + OFF_W3,  wtl + OFF_W3,  D_, HID_);
        prep_weight_kernel<<<dim3(32, 88), blk>>>(w2,  wth + OFF_W2,  wtl + OFF_W2,  HID_, D_);
    }

    // ---- Upfront: all-step QKV projections + RoPE ----
    mma_gemm_kernel<128, 128, false, false><<<dim3(24, 32, 2), 256, SMEM_OF(128, 128)>>>(
        x, nullptr, SD,
        wth + OFF_WQ, wth + OFF_WK, wth + OFF_WV,
        wtl + OFF_WQ, wtl + OFF_WK, wtl + OFF_WV,
        p_qx, p_kx, p_vx, SD, SD, SD, D_, D_, 8);
    {
        int n = B_ * S_ * (D_ / 2);
        rope_kernel<<<(n + 255) / 256, 256>>>(p_qx, cosT, sinT, 512, M_, n);
        rope_kernel<<<(n + 255) / 256, 256>>>(p_kx, cosT, sinT, 512, M_, n);
    }

    // ---- Sequential memory chain ----
    for (int s = 0; s < NSTEP; s++) {
        const float* om = (s == 0) ? omem : (p_allout + (size_t)(s - 1) * M_ * D_);
        const long long omB = (s == 0) ? 0LL : SD;

        // a = om @ wm
        mma_gemm_kernel<64, 64, false, false><<<dim3(16, 8, 2), 256, SMEM_OF(64, 64)>>>(
            om, nullptr, omB,
            wth + OFF_WM, wth + OFF_WM, wth + OFF_WM,
            wtl + OFF_WM, wtl + OFF_WM, wtl + OFF_WM,
            p_a, p_a, p_a, MD, MD, MD, D_, D_, 16);
        // hn = rmsnorm(a, ffn_norm_w)
        rmsnorm_kernel<<<B_ * M_, 256>>>(p_a, ffn_nw, p_hn);
        // t1 = hn @ w1 ; t3 = hn @ w3 (raw, gate fused into w2 GEMM)
        mma_gemm_kernel<64, 128, false, false><<<dim3(44, 8, 2), 256, SMEM_OF(64, 128)>>>(
            p_hn, nullptr, MD,
            wth + OFF_W1, wth + OFF_W3, wth + OFF_W3,
            wtl + OFF_W1, wtl + OFF_W3, wtl + OFF_W3,
            p_t1, p_t3, p_t3, MH, MH, MH, D_, HID_, 22);
        // a += silu(t1)*t3 @ w2   (gate fused into A-load)
        mma_gemm_kernel<64, 64, true, true><<<dim3(16, 8, 2), 256, SMEM_OF(64, 64)>>>(
            p_t1, p_t3, MH,
            wth + OFF_W2, wth + OFF_W2, wth + OFF_W2,
            wtl + OFF_W2, wtl + OFF_W2, wtl + OFF_W2,
            p_a, p_a, p_a, MD, MD, MD, HID_, D_, 16);
        // m2 = rmsnorm(a, mem_norm_w)
        rmsnorm_kernel<<<B_ * M_, 256>>>(p_a, mem_nw, p_m2);
        // mk, mv (fused)
        mma_gemm_kernel<64, 128, false, false><<<dim3(16, 8, 2), 256, SMEM_OF(64, 128)>>>(
            p_m2, nullptr, MD,
            wth + OFF_WKM, wth + OFF_WVM, wth + OFF_WVM,
            wtl + OFF_WKM, wtl + OFF_WVM, wtl + OFF_WVM,
            p_k, p_v, p_v, MD, MD, MD, D_, D_, 8);
        // RoPE on mk (positions 0..511)
        {
            int n = B_ * M_ * (D_ / 2);
            rope_kernel<<<(n + 255) / 256, 256>>>(p_k, cosT, sinT, 512, 0, n);
        }
        // Attention
        attn_kernel<<<dim3(M_ / 64, H_, B_), 256, ATTN_SMEM>>>(
            p_qx, p_k, p_v, p_kx, p_vx, p_allout, s * M_);
    }

    // out = allout @ wo
    mma_gemm_kernel<128, 128, false, false><<<dim3(8, 64, 1), 256, SMEM_OF(128, 128)>>>(
        p_allout, nullptr, 0LL,
        wth + OFF_WO, wth + OFF_WO, wth + OFF_WO,
        wtl + OFF_WO, wtl + OFF_WO, wtl + OFF_WO,
        out, out, out, 0LL, 0LL, 0LL, D_, D_, 8);
}

// round 13
// speedup vs baseline: 1.0380x; 1.0380x over previous
#include <cuda_runtime.h>
#include <cuda_bf16.h>
#include <cstdint>
#include <math.h>

// Problem constants
#define B_  2
#define S_  4096
#define D_  1024
#define H_  16
#define HD_ 64
#define M_  512
#define L_  1024
#define HID_ 2816
#define NSTEP 8

// ---------------------------------------------------------------------------
// Scratch (device globals; no allocation allowed)
// ---------------------------------------------------------------------------
__device__ float g_allout[B_ * S_ * D_];
__device__ float g_qx[B_ * S_ * D_];
__device__ float g_kx[B_ * S_ * D_];
__device__ float g_vx[B_ * S_ * D_];
__device__ float g_a  [B_ * M_ * D_];
__device__ float g_hn [B_ * M_ * D_];
__device__ float g_t1 [B_ * M_ * HID_];
__device__ float g_t3 [B_ * M_ * HID_];
__device__ float g_m2 [B_ * M_ * D_];
__device__ float g_k  [B_ * M_ * D_];
__device__ float g_v  [B_ * M_ * D_];

// Pre-split, pre-transposed weights: [n][k] bf16 hi/lo planes
#define OFF_WM  0LL
#define OFF_WKM 1048576LL
#define OFF_WVM 2097152LL
#define OFF_WQ  3145728LL
#define OFF_WK  4194304LL
#define OFF_WV  5242880LL
#define OFF_WO  6291456LL
#define OFF_W1  7340032LL
#define OFF_W3  10223616LL
#define OFF_W2  13107200LL
#define WT_ELEMS 15990784LL
__device__ __nv_bfloat16 g_wth[WT_ELEMS];
__device__ __nv_bfloat16 g_wtl[WT_ELEMS];

// ---------------------------------------------------------------------------
// Warp-level bf16 MMA + ldmatrix helpers (valid under compute_103 target)
// ---------------------------------------------------------------------------
__device__ __forceinline__ void mma16816(float* c,
                                         uint32_t a0, uint32_t a1, uint32_t a2, uint32_t a3,
                                         uint32_t b0, uint32_t b1)
{
    asm volatile(
        "mma.sync.aligned.m16n8k16.row.col.f32.bf16.bf16.f32 "
        "{%0,%1,%2,%3}, {%4,%5,%6,%7}, {%8,%9}, {%0,%1,%2,%3};"
        : "+f"(c[0]), "+f"(c[1]), "+f"(c[2]), "+f"(c[3])
        : "r"(a0), "r"(a1), "r"(a2), "r"(a3), "r"(b0), "r"(b1));
}

__device__ __forceinline__ void ldsm4(uint32_t& r0, uint32_t& r1,
                                      uint32_t& r2, uint32_t& r3, uint32_t addr)
{
    asm volatile("ldmatrix.sync.aligned.m8n8.x4.shared.b16 {%0,%1,%2,%3}, [%4];"
        : "=r"(r0), "=r"(r1), "=r"(r2), "=r"(r3) : "r"(addr));
}

__device__ __forceinline__ uint32_t smem_u32(const void* p) {
    uint32_t a;
    asm("{ .reg .u64 t; cvta.to.shared.u64 t, %1; cvt.u32.u64 %0, t; }"
        : "=r"(a) : "l"(p));
    return a;
}

// ---------------------------------------------------------------------------
// Weight prep: W (K x N fp32, row-major) -> Wh/Wl (N x K bf16, row-major)
// ---------------------------------------------------------------------------
__global__ __launch_bounds__(256)
void prep_weight_kernel(const float* __restrict__ W,
                        __nv_bfloat16* __restrict__ Wh,
                        __nv_bfloat16* __restrict__ Wl,
                        int K, int N)
{
    __shared__ float t[32][33];
    const int n0 = blockIdx.x * 32, k0 = blockIdx.y * 32;
    const int tx = threadIdx.x, ty = threadIdx.y;
    #pragma unroll
    for (int i = 0; i < 4; i++)
        t[ty + i * 8][tx] = W[(size_t)(k0 + ty + i * 8) * N + n0 + tx];
    __syncthreads();
    #pragma unroll
    for (int i = 0; i < 4; i++) {
        int n = n0 + ty + i * 8, k = k0 + tx;
        float v = t[tx][ty + i * 8];
        __nv_bfloat16 h = __float2bfloat16(v);
        Wh[(size_t)n * K + k] = h;
        Wl[(size_t)n * K + k] = __float2bfloat16(v - __bfloat162float(h));
    }
}

// ---------------------------------------------------------------------------
// Split-bf16 GEMM, pre-transposed bf16 B planes.
// C[z][mat] = A[z] (rows x K fp32) @ Bt[mat]^T  (Bt is N x K bf16 hi/lo)
// acc = Ah*Bh + Ah*Bl + Al*Bh. Tile TM x TN, BK=32, 256 threads (2M x 4N warps).
// ---------------------------------------------------------------------------
#define BK 32
#define AST 40
#define ASTB (AST * 2)

template <int TM, int TN, bool ACC>
__global__ __launch_bounds__(256, 2)
void mma_gemm_kernel(const float* __restrict__ A, long long aBatch,
                     const __nv_bfloat16* __restrict__ Bh0,
                     const __nv_bfloat16* __restrict__ Bh1,
                     const __nv_bfloat16* __restrict__ Bh2,
                     const __nv_bfloat16* __restrict__ Bl0,
                     const __nv_bfloat16* __restrict__ Bl1,
                     const __nv_bfloat16* __restrict__ Bl2,
                     float* __restrict__ C0, float* __restrict__ C1, float* __restrict__ C2,
                     long long cB0, long long cB1, long long cB2,
                     int K, int N, int tilesN)
{
    constexpr int WM = TM / 2;
    constexpr int WN = TN / 4;
    constexpr int MT = WM / 16;
    constexpr int NT = WN / 8;
    constexpr int P  = NT / 2;
    constexpr int A_HALF = TM * AST * 2;
    constexpr int B_HALF = TN * AST * 2;
    constexpr int CA  = TM / 32;        // A float4 loads per thread
    constexpr int TPR = 256 / TM;       // threads per A row
    constexpr int TPRB = 256 / TN;      // threads per B row
    constexpr int EB  = 32 / TPRB;      // bf16 elems per thread per plane
    constexpr int V4  = EB / 8;         // uint4 loads per plane

    extern __shared__ char smem[];
    __nv_bfloat16* Ahi = (__nv_bfloat16*)smem;
    __nv_bfloat16* Alo = (__nv_bfloat16*)(smem + A_HALF);
    __nv_bfloat16* Bhi = (__nv_bfloat16*)(smem + 2 * A_HALF);
    __nv_bfloat16* Blo = (__nv_bfloat16*)(smem + 2 * A_HALF + B_HALF);

    const int tid = threadIdx.x;
    const int wid = tid >> 5, lane = tid & 31;
    const int wm = wid & 1, wn = wid >> 1;
    const int r  = lane >> 2, qc = (lane & 3) * 2;

    const int tn  = blockIdx.x % tilesN;
    const int mat = blockIdx.x / tilesN;
    const int bz  = blockIdx.z;
    const int m0  = blockIdx.y * TM;
    const int n0  = tn * TN;

    const __nv_bfloat16* Bth = (mat == 0) ? Bh0 : ((mat == 1) ? Bh1 : Bh2);
    const __nv_bfloat16* Btl = (mat == 0) ? Bl0 : ((mat == 1) ? Bl1 : Bl2);
    float*       Cm = (mat == 0) ? C0 : ((mat == 1) ? C1 : C2);
    const long long cB = (mat == 0) ? cB0 : ((mat == 1) ? cB1 : cB2);

    const float* Ab = A + (long long)bz * aBatch + (long long)m0 * K;

    const uint32_t sAhi = smem_u32(Ahi);
    const uint32_t sBhi = smem_u32(Bhi);
    const uint32_t aLaneOff = (uint32_t)((lane & 15) * AST + (lane >> 4) * 8) * 2;
    const uint32_t bLaneOff = (uint32_t)((((lane & 7) + ((lane >> 4) << 3)) * AST
                                          + ((lane >> 3) & 1) * 8) * 2);

    const int ar  = tid / TPR,  akb = (tid % TPR) * (32 / TPR);
    const int brow = tid / TPRB, bkp = tid % TPRB;

    const __nv_bfloat16* Bph = Bth + (size_t)(n0 + brow) * K + bkp * EB;
    const __nv_bfloat16* Bpl = Btl + (size_t)(n0 + brow) * K + bkp * EB;

    float4 pa[CA];
    uint4  pbh[V4], pbl[V4];
    {
        const float* Ap = Ab + (size_t)ar * K + akb;
        #pragma unroll
        for (int j = 0; j < CA; j++) pa[j] = *(const float4*)(Ap + j * 4);
        #pragma unroll
        for (int v = 0; v < V4; v++) {
            pbh[v] = *(const uint4*)(Bph + v * 8);
            pbl[v] = *(const uint4*)(Bpl + v * 8);
        }
    }

    float acc[MT][NT][4];
    #pragma unroll
    for (int i = 0; i < MT; i++)
        #pragma unroll
        for (int j = 0; j < NT; j++)
            #pragma unroll
            for (int e = 0; e < 4; e++) acc[i][j][e] = 0.f;

    const int NC = K / BK;
    #pragma unroll 1
    for (int kc = 0; kc < NC; kc++) {
        // ---- A: convert + split-store ----
        #pragma unroll
        for (int j = 0; j < CA; j++) {
            float4 v = pa[j];
            __nv_bfloat16 h0 = __float2bfloat16(v.x);
            __nv_bfloat16 h1 = __float2bfloat16(v.y);
            __nv_bfloat16 h2 = __float2bfloat16(v.z);
            __nv_bfloat16 h3 = __float2bfloat16(v.w);
            __nv_bfloat162 hp0 = __halves2bfloat162(h0, h1);
            __nv_bfloat162 hp1 = __halves2bfloat162(h2, h3);
            __nv_bfloat162 lp0 = __floats2bfloat162_rn(v.x - __bfloat162float(h0),
                                                       v.y - __bfloat162float(h1));
            __nv_bfloat162 lp1 = __floats2bfloat162_rn(v.z - __bfloat162float(h2),
                                                       v.w - __bfloat162float(h3));
            int off = ar * AST + akb + j * 4;
            *(uint2*)&Ahi[off] = make_uint2(*(uint32_t*)&hp0, *(uint32_t*)&hp1);
            *(uint2*)&Alo[off] = make_uint2(*(uint32_t*)&lp0, *(uint32_t*)&lp1);
        }
        // ---- B: direct vector copy of pre-split planes ----
        #pragma unroll
        for (int v = 0; v < V4; v++) {
            int off = brow * AST + bkp * EB + v * 8;
            *(uint2*)&Bhi[off]     = make_uint2(pbh[v].x, pbh[v].y);
            *(uint2*)&Bhi[off + 4] = make_uint2(pbh[v].z, pbh[v].w);
            *(uint2*)&Blo[off]     = make_uint2(pbl[v].x, pbl[v].y);
            *(uint2*)&Blo[off + 4] = make_uint2(pbl[v].z, pbl[v].w);
        }
        __syncthreads();

        // ---- prefetch next chunk ----
        if (kc + 1 < NC) {
            const int k0n = (kc + 1) * BK;
            const float* Ap = Ab + (size_t)ar * K + k0n + akb;
            #pragma unroll
            for (int j = 0; j < CA; j++) pa[j] = *(const float4*)(Ap + j * 4);
            #pragma unroll
            for (int v = 0; v < V4; v++) {
                pbh[v] = *(const uint4*)(Bph + k0n + v * 8);
                pbl[v] = *(const uint4*)(Bpl + k0n + v * 8);
            }
        }

        // ---- MMA: 2 k-steps of 16, fragments via ldmatrix ----
        #pragma unroll
        for (int ks = 0; ks < 2; ks++) {
            const uint32_t kOff = ks * 32;
            uint32_t bh[P][4], bl[P][4];
            #pragma unroll
            for (int p = 0; p < P; p++) {
                uint32_t baddr = sBhi + (uint32_t)(wn * WN + p * 16) * ASTB + kOff + bLaneOff;
                ldsm4(bh[p][0], bh[p][1], bh[p][2], bh[p][3], baddr);
                ldsm4(bl[p][0], bl[p][1], bl[p][2], bl[p][3], baddr + B_HALF);
            }
            #pragma unroll
            for (int mt = 0; mt < MT; mt++) {
                uint32_t aaddr = sAhi + (uint32_t)(wm * WM + mt * 16) * ASTB + kOff + aLaneOff;
                uint32_t ah0, ah1, ah2, ah3, al0, al1, al2, al3;
                ldsm4(ah0, ah1, ah2, ah3, aaddr);
                ldsm4(al0, al1, al2, al3, aaddr + A_HALF);
                #pragma unroll
                for (int nt = 0; nt < NT; nt++) {
                    uint32_t b0 = bh[nt >> 1][(nt & 1) * 2];
                    uint32_t b1 = bh[nt >> 1][(nt & 1) * 2 + 1];
                    uint32_t c0 = bl[nt >> 1][(nt & 1) * 2];
                    uint32_t c1 = bl[nt >> 1][(nt & 1) * 2 + 1];
                    mma16816(acc[mt][nt], ah0, ah1, ah2, ah3, b0, b1);
                    mma16816(acc[mt][nt], ah0, ah1, ah2, ah3, c0, c1);
                    mma16816(acc[mt][nt], al0, al1, al2, al3, b0, b1);
                }
            }
        }
        __syncthreads();
    }

    // ---- epilogue ----
    float* Cb = Cm + (long long)bz * cB;
    #pragma unroll
    for (int mt = 0; mt < MT; mt++) {
        int row0 = m0 + wm * WM + mt * 16 + r;
        #pragma unroll
        for (int nt = 0; nt < NT; nt++) {
            int col = n0 + wn * WN + nt * 8 + qc;
            float* p0 = Cb + (size_t)row0 * N + col;
            float* p1 = Cb + (size_t)(row0 + 8) * N + col;
            float2 v0 = make_float2(acc[mt][nt][0], acc[mt][nt][1]);
            float2 v1 = make_float2(acc[mt][nt][2], acc[mt][nt][3]);
            if (ACC) {
                float2 o0 = *(const float2*)p0;
                float2 o1 = *(const float2*)p1;
                v0.x += o0.x; v0.y += o0.y;
                v1.x += o1.x; v1.y += o1.y;
            }
            *(float2*)p0 = v0;
            *(float2*)p1 = v1;
        }
    }
}

#define SMEM_OF(TM, TN) (2 * (TM) * AST * 2 + 2 * (TN) * AST * 2)

// ---------------------------------------------------------------------------
// RMSNorm
// ---------------------------------------------------------------------------
__global__ __launch_bounds__(256)
void rmsnorm_kernel(const float* __restrict__ x, const float* __restrict__ w,
                    float* __restrict__ o)
{
    const int row = blockIdx.x;
    const int tid = threadIdx.x;
    const float4 v = *(const float4*)(x + (size_t)row * D_ + tid * 4);
    float ss = v.x * v.x + v.y * v.y + v.z * v.z + v.w * v.w;
    #pragma unroll
    for (int off = 16; off; off >>= 1)
        ss += __shfl_xor_sync(0xffffffffu, ss, off);
    __shared__ float ws[8];
    __shared__ float s_inv;
    if ((tid & 31) == 0) ws[tid >> 5] = ss;
    __syncthreads();
    if (tid == 0) {
        float t = 0.f;
        #pragma unroll
        for (int i = 0; i < 8; i++) t += ws[i];
        s_inv = rsqrtf(t * (1.0f / D_) + 1e-5f);
    }
    __syncthreads();
    const float inv = s_inv;
    const float4 wv = *(const float4*)(w + tid * 4);
    float4 ov;
    ov.x = v.x * inv * wv.x;
    ov.y = v.y * inv * wv.y;
    ov.z = v.z * inv * wv.z;
    ov.w = v.w * inv * wv.w;
    *(float4*)(o + (size_t)row * D_ + tid * 4) = ov;
}

// ---------------------------------------------------------------------------
// SwiGLU gate (float4)
// ---------------------------------------------------------------------------
__global__ void silu_gate_kernel(float4* __restrict__ t1,
                                 const float4* __restrict__ t3, int n4)
{
    int i = blockIdx.x * blockDim.x + threadIdx.x;
    if (i < n4) {
        float4 a = t1[i];
        float4 b = t3[i];
        float4 o;
        o.x = (a.x / (1.f + __expf(-a.x))) * b.x;
        o.y = (a.y / (1.f + __expf(-a.y))) * b.y;
        o.z = (a.z / (1.f + __expf(-a.z))) * b.z;
        o.w = (a.w / (1.f + __expf(-a.w))) * b.w;
        t1[i] = o;
    }
}

// ---------------------------------------------------------------------------
// RoPE: rows of width 1024; position = posOff + (row % rowsMod)
// ---------------------------------------------------------------------------
__global__ void rope_kernel(float* __restrict__ t,
                            const float* __restrict__ cosT,
                            const float* __restrict__ sinT,
                            int rowsMod, int posOff, int nPairs)
{
    int id = blockIdx.x * blockDim.x + threadIdx.x;
    if (id >= nPairs) return;
    int pair = id & 511;
    int row  = id >> 9;
    int pos  = posOff + (row % rowsMod);
    int i    = pair & 31;
    float c = cosT[pos * 32 + i];
    float s = sinT[pos * 32 + i];
    float2* p = (float2*)(t + (size_t)row * D_ + pair * 2);
    float2 v = *p;
    float2 o;
    o.x = v.x * c - v.y * s;
    o.y = v.x * s + v.y * c;
    *p = o;
}

// ---------------------------------------------------------------------------
// Flash-style causal attention (x-part queries only).
// ---------------------------------------------------------------------------
#define ALD 65
#define ATTN_SMEM ((4 * 64 * ALD + 3 * 64) * (int)sizeof(float))

__global__ __launch_bounds__(256)
void attn_kernel(const float* __restrict__ Qx,
                 const float* __restrict__ Km, const float* __restrict__ Vm,
                 const float* __restrict__ Kx, const float* __restrict__ Vx,
                 float* __restrict__ Out, int sBase)
{
    extern __shared__ float sm[];
    float* Qs   = sm;
    float* Ks   = Qs + 64 * ALD;
    float* Vs   = Ks + 64 * ALD;
    float* Ss   = Vs + 64 * ALD;
    float* mrow = Ss + 64 * ALD;
    float* lrow = mrow + 64;
    float* crow = lrow + 64;

    const int b  = blockIdx.z;
    const int h  = blockIdx.y;
    const int qt = blockIdx.x;
    const int tid = threadIdx.x;
    const int tx = tid & 15, ty = tid >> 4;
    const int q0 = qt * 64;
    const float scale = 0.125f;

    for (int e = tid; e < 64 * 16; e += 256) {
        int i = e >> 4, d4 = (e & 15) * 4;
        float4 v = *(const float4*)&Qx[((size_t)(b * S_ + sBase + q0 + i)) * D_ + h * HD_ + d4];
        Qs[i * ALD + d4 + 0] = v.x;
        Qs[i * ALD + d4 + 1] = v.y;
        Qs[i * ALD + d4 + 2] = v.z;
        Qs[i * ALD + d4 + 3] = v.w;
    }
    if (tid < 64) { mrow[tid] = -1e30f; lrow[tid] = 0.f; }
    float acc[4][4];
    #pragma unroll
    for (int i = 0; i < 4; i++)
        #pragma unroll
        for (int j = 0; j < 4; j++) acc[i][j] = 0.f;
    __syncthreads();

    const int nkt = qt + 9;
    for (int kt = 0; kt < nkt; kt++) {
        const float* Kp;
        const float* Vp;
        size_t rb;
        if (kt < 8) {
            Kp = Km; Vp = Vm;
            rb = (size_t)(b * M_ + kt * 64);
        } else {
            Kp = Kx; Vp = Vx;
            rb = (size_t)(b * S_ + sBase + (kt - 8) * 64);
        }
        for (int e = tid; e < 64 * 16; e += 256) {
            int j = e >> 4, d4 = (e & 15) * 4;
            size_t base = (rb + j) * D_ + h * HD_ + d4;
            float4 kv = *(const float4*)&Kp[base];
            Ks[j * ALD + d4 + 0] = kv.x;
            Ks[j * ALD + d4 + 1] = kv.y;
            Ks[j * ALD + d4 + 2] = kv.z;
            Ks[j * ALD + d4 + 3] = kv.w;
            float4 vv = *(const float4*)&Vp[base];
            Vs[j * ALD + d4 + 0] = vv.x;
            Vs[j * ALD + d4 + 1] = vv.y;
            Vs[j * ALD + d4 + 2] = vv.z;
            Vs[j * ALD + d4 + 3] = vv.w;
        }
        __syncthreads();

        float s4[4][4];
        #pragma unroll
        for (int i = 0; i < 4; i++)
            #pragma unroll
            for (int j = 0; j < 4; j++) s4[i][j] = 0.f;
        for (int d = 0; d < 64; d++) {
            float rq[4], rk[4];
            #pragma unroll
            for (int ii = 0; ii < 4; ii++) rq[ii] = Qs[(ty * 4 + ii) * ALD + d];
            #pragma unroll
            for (int jj = 0; jj < 4; jj++) rk[jj] = Ks[(tx * 4 + jj) * ALD + d];
            #pragma unroll
            for (int ii = 0; ii < 4; ii++)
                #pragma unroll
                for (int jj = 0; jj < 4; jj++)
                    s4[ii][jj] = fmaf(rq[ii], rk[jj], s4[ii][jj]);
        }
        const int qg0 = M_ + q0;
        #pragma unroll
        for (int ii = 0; ii < 4; ii++) {
            int qi = qg0 + ty * 4 + ii;
            #pragma unroll
            for (int jj = 0; jj < 4; jj++) {
                int kj = kt * 64 + tx * 4 + jj;
                float val = (kj <= qi) ? s4[ii][jj] * scale : -1e30f;
                Ss[(ty * 4 + ii) * ALD + tx * 4 + jj] = val;
            }
        }
        __syncthreads();

        if (tid < 64) {
            float mold = mrow[tid];
            float mx = mold;
            for (int j = 0; j < 64; j++) mx = fmaxf(mx, Ss[tid * ALD + j]);
            float c = __expf(mold - mx);
            float sum = 0.f;
            for (int j = 0; j < 64; j++) {
                float p = __expf(Ss[tid * ALD + j] - mx);
                Ss[tid * ALD + j] = p;
                sum += p;
            }
            mrow[tid] = mx;
            lrow[tid] = lrow[tid] * c + sum;
            crow[tid] = c;
        }
        __syncthreads();

        float cc[4];
        #pragma unroll
        for (int ii = 0; ii < 4; ii++) cc[ii] = crow[ty * 4 + ii];
        #pragma unroll
        for (int ii = 0; ii < 4; ii++)
            #pragma unroll
            for (int dd = 0; dd < 4; dd++) acc[ii][dd] *= cc[ii];
        for (int j = 0; j < 64; j++) {
            float rp[4], rv[4];
            #pragma unroll
            for (int ii = 0; ii < 4; ii++) rp[ii] = Ss[(ty * 4 + ii) * ALD + j];
            #pragma unroll
            for (int dd = 0; dd < 4; dd++) rv[dd] = Vs[j * ALD + tx * 4 + dd];
            #pragma unroll
            for (int ii = 0; ii < 4; ii++)
                #pragma unroll
                for (int dd = 0; dd < 4; dd++)
                    acc[ii][dd] = fmaf(rp[ii], rv[dd], acc[ii][dd]);
        }
        __syncthreads();
    }

    if (tid < 64) crow[tid] = 1.f / lrow[tid];
    __syncthreads();
    #pragma unroll
    for (int ii = 0; ii < 4; ii++) {
        float inv = crow[ty * 4 + ii];
        int grow = b * S_ + sBase + q0 + ty * 4 + ii;
        float4 o;
        o.x = acc[ii][0] * inv;
        o.y = acc[ii][1] * inv;
        o.z = acc[ii][2] * inv;
        o.w = acc[ii][3] * inv;
        *(float4*)&Out[(size_t)grow * D_ + h * HD_ + tx * 4] = o;
    }
}

// ---------------------------------------------------------------------------
// Launch
// ---------------------------------------------------------------------------
extern "C" void kernel_launch(void* const* d_in, const int* in_sizes, int n_in,
                              void* d_out, int out_size)
{
    const float* x        = (const float*)d_in[0];
    const float* cosT     = (const float*)d_in[1];
    const float* sinT     = (const float*)d_in[2];
    const float* wq       = (const float*)d_in[3];
    const float* wk       = (const float*)d_in[4];
    const float* wv       = (const float*)d_in[5];
    const float* wo       = (const float*)d_in[6];
    const float* wm       = (const float*)d_in[7];
    const float* wkm      = (const float*)d_in[8];
    const float* wvm      = (const float*)d_in[9];
    const float* w1       = (const float*)d_in[10];
    const float* w3       = (const float*)d_in[11];
    const float* w2       = (const float*)d_in[12];
    const float* ffn_nw   = (const float*)d_in[13];
    const float* mem_nw   = (const float*)d_in[14];
    const float* omem     = (const float*)d_in[15];
    float* out = (float*)d_out;

    float *p_allout, *p_qx, *p_kx, *p_vx, *p_a, *p_hn, *p_t1, *p_t3, *p_m2, *p_k, *p_v;
    __nv_bfloat16 *wth, *wtl;
    cudaGetSymbolAddress((void**)&p_allout, g_allout);
    cudaGetSymbolAddress((void**)&p_qx, g_qx);
    cudaGetSymbolAddress((void**)&p_kx, g_kx);
    cudaGetSymbolAddress((void**)&p_vx, g_vx);
    cudaGetSymbolAddress((void**)&p_a,  g_a);
    cudaGetSymbolAddress((void**)&p_hn, g_hn);
    cudaGetSymbolAddress((void**)&p_t1, g_t1);
    cudaGetSymbolAddress((void**)&p_t3, g_t3);
    cudaGetSymbolAddress((void**)&p_m2, g_m2);
    cudaGetSymbolAddress((void**)&p_k,  g_k);
    cudaGetSymbolAddress((void**)&p_v,  g_v);
    cudaGetSymbolAddress((void**)&wth,  g_wth);
    cudaGetSymbolAddress((void**)&wtl,  g_wtl);

    cudaFuncSetAttribute(attn_kernel,
                         cudaFuncAttributeMaxDynamicSharedMemorySize, ATTN_SMEM);
    cudaFuncSetAttribute(mma_gemm_kernel<128, 128, false>,
                         cudaFuncAttributeMaxDynamicSharedMemorySize, SMEM_OF(128, 128));
    cudaFuncSetAttribute(mma_gemm_kernel<64, 64, false>,
                         cudaFuncAttributeMaxDynamicSharedMemorySize, SMEM_OF(64, 64));
    cudaFuncSetAttribute(mma_gemm_kernel<64, 128, false>,
                         cudaFuncAttributeMaxDynamicSharedMemorySize, SMEM_OF(64, 128));
    cudaFuncSetAttribute(mma_gemm_kernel<64, 64, true>,
                         cudaFuncAttributeMaxDynamicSharedMemorySize, SMEM_OF(64, 64));

    const long long MD  = (long long)M_ * D_;
    const long long MH  = (long long)M_ * HID_;
    const long long SD  = (long long)S_ * D_;

    // ---- Prep: split + transpose all weights into bf16 hi/lo planes ----
    {
        dim3 blk(32, 8);
        prep_weight_kernel<<<dim3(32, 32), blk>>>(wm,  wth + OFF_WM,  wtl + OFF_WM,  D_, D_);
        prep_weight_kernel<<<dim3(32, 32), blk>>>(wkm, wth + OFF_WKM, wtl + OFF_WKM, D_, D_);
        prep_weight_kernel<<<dim3(32, 32), blk>>>(wvm, wth + OFF_WVM, wtl + OFF_WVM, D_, D_);
        prep_weight_kernel<<<dim3(32, 32), blk>>>(wq,  wth + OFF_WQ,  wtl + OFF_WQ,  D_, D_);
        prep_weight_kernel<<<dim3(32, 32), blk>>>(wk,  wth + OFF_WK,  wtl + OFF_WK,  D_, D_);
        prep_weight_kernel<<<dim3(32, 32), blk>>>(wv,  wth + OFF_WV,  wtl + OFF_WV,  D_, D_);
        prep_weight_kernel<<<dim3(32, 32), blk>>>(wo,  wth + OFF_WO,  wtl + OFF_WO,  D_, D_);
        prep_weight_kernel<<<dim3(88, 32), blk>>>(w1,  wth + OFF_W1,  wtl + OFF_W1,  D_, HID_);
        prep_weight_kernel<<<dim3(88, 32), blk>>>(w3,  wth + OFF_W3,  wtl + OFF_W3,  D_, HID_);
        prep_weight_kernel<<<dim3(32, 88), blk>>>(w2,  wth + OFF_W2,  wtl + OFF_W2,  HID_, D_);
    }

    // ---- Upfront: all-step QKV projections + RoPE ----
    mma_gemm_kernel<128, 128, false><<<dim3(24, 32, 2), 256, SMEM_OF(128, 128)>>>(
        x, SD,
        wth + OFF_WQ, wth + OFF_WK, wth + OFF_WV,
        wtl + OFF_WQ, wtl + OFF_WK, wtl + OFF_WV,
        p_qx, p_kx, p_vx, SD, SD, SD, D_, D_, 8);
    {
        int n = B_ * S_ * (D_ / 2);
        rope_kernel<<<(n + 255) / 256, 256>>>(p_qx, cosT, sinT, 512, M_, n);
        rope_kernel<<<(n + 255) / 256, 256>>>(p_kx, cosT, sinT, 512, M_, n);
    }

    // ---- Sequential memory chain ----
    for (int s = 0; s < NSTEP; s++) {
        const float* om = (s == 0) ? omem : (p_allout + (size_t)(s - 1) * M_ * D_);
        const long long omB = (s == 0) ? 0LL : SD;

        // a = om @ wm
        mma_gemm_kernel<64, 64, false><<<dim3(16, 8, 2), 256, SMEM_OF(64, 64)>>>(
            om, omB,
            wth + OFF_WM, wth + OFF_WM, wth + OFF_WM,
            wtl + OFF_WM, wtl + OFF_WM, wtl + OFF_WM,
            p_a, p_a, p_a, MD, MD, MD, D_, D_, 16);
        // hn = rmsnorm(a, ffn_norm_w)
        rmsnorm_kernel<<<B_ * M_, 256>>>(p_a, ffn_nw, p_hn);
        // t1 = hn @ w1 ; t3 = hn @ w3 (fused)
        mma_gemm_kernel<64, 128, false><<<dim3(44, 8, 2), 256, SMEM_OF(64, 128)>>>(
            p_hn, MD,
            wth + OFF_W1, wth + OFF_W3, wth + OFF_W3,
            wtl + OFF_W1, wtl + OFF_W3, wtl + OFF_W3,
            p_t1, p_t3, p_t3, MH, MH, MH, D_, HID_, 22);
        // t1 = silu(t1) * t3
        silu_gate_kernel<<<(B_ * M_ * HID_ / 4 + 255) / 256, 256>>>(
            (float4*)p_t1, (const float4*)p_t3, B_ * M_ * HID_ / 4);
        // a += t1 @ w2
        mma_gemm_kernel<64, 64, true><<<dim3(16, 8, 2), 256, SMEM_OF(64, 64)>>>(
            p_t1, MH,
            wth + OFF_W2, wth + OFF_W2, wth + OFF_W2,
            wtl + OFF_W2, wtl + OFF_W2, wtl + OFF_W2,
            p_a, p_a, p_a, MD, MD, MD, HID_, D_, 16);
        // m2 = rmsnorm(a, mem_norm_w)
        rmsnorm_kernel<<<B_ * M_, 256>>>(p_a, mem_nw, p_m2);
        // mk, mv (fused)
        mma_gemm_kernel<64, 128, false><<<dim3(16, 8, 2), 256, SMEM_OF(64, 128)>>>(
            p_m2, MD,
            wth + OFF_WKM, wth + OFF_WVM, wth + OFF_WVM,
            wtl + OFF_WKM, wtl + OFF_WVM, wtl + OFF_WVM,
            p_k, p_v, p_v, MD, MD, MD, D_, D_, 8);
        // RoPE on mk (positions 0..511)
        {
            int n = B_ * M_ * (D_ / 2);
            rope_kernel<<<(n + 255) / 256, 256>>>(p_k, cosT, sinT, 512, 0, n);
        }
        // Attention
        attn_kernel<<<dim3(M_ / 64, H_, B_), 256, ATTN_SMEM>>>(
            p_qx, p_k, p_v, p_kx, p_vx, p_allout, s * M_);
    }

    // out = allout @ wo
    mma_gemm_kernel<128, 128, false><<<dim3(8, 64, 1), 256, SMEM_OF(128, 128)>>>(
        p_allout, 0LL,
        wth + OFF_WO, wth + OFF_WO, wth + OFF_WO,
        wtl + OFF_WO, wtl + OFF_WO, wtl + OFF_WO,
        out, out, out, 0LL, 0LL, 0LL, D_, D_, 8);
}

// round 14
// speedup vs baseline: 1.3167x; 1.2685x over previous
#include <cuda_runtime.h>
#include <cuda_bf16.h>
#include <cstdint>
#include <math.h>

// Problem constants
#define B_  2
#define S_  4096
#define D_  1024
#define H_  16
#define HD_ 64
#define M_  512
#define L_  1024
#define HID_ 2816
#define NSTEP 8

// ---------------------------------------------------------------------------
// Scratch (device globals; no allocation allowed)
// ---------------------------------------------------------------------------
__device__ float g_allout[B_ * S_ * D_];
__device__ float g_qx[B_ * S_ * D_];
__device__ float g_kx[B_ * S_ * D_];
__device__ float g_vx[B_ * S_ * D_];
__device__ float g_a  [B_ * M_ * D_];
__device__ float g_hn [B_ * M_ * D_];
__device__ float g_t1 [B_ * M_ * HID_];
__device__ float g_t3 [B_ * M_ * HID_];
__device__ float g_m2 [B_ * M_ * D_];
__device__ float g_k  [B_ * M_ * D_];
__device__ float g_v  [B_ * M_ * D_];

// ---------------------------------------------------------------------------
// Warp-level bf16 MMA + ldmatrix helpers (valid under compute_103 target)
// ---------------------------------------------------------------------------
__device__ __forceinline__ void mma16816(float* c,
                                         uint32_t a0, uint32_t a1, uint32_t a2, uint32_t a3,
                                         uint32_t b0, uint32_t b1)
{
    asm volatile(
        "mma.sync.aligned.m16n8k16.row.col.f32.bf16.bf16.f32 "
        "{%0,%1,%2,%3}, {%4,%5,%6,%7}, {%8,%9}, {%0,%1,%2,%3};"
        : "+f"(c[0]), "+f"(c[1]), "+f"(c[2]), "+f"(c[3])
        : "r"(a0), "r"(a1), "r"(a2), "r"(a3), "r"(b0), "r"(b1));
}

__device__ __forceinline__ void ldsm4(uint32_t& r0, uint32_t& r1,
                                      uint32_t& r2, uint32_t& r3, uint32_t addr)
{
    asm volatile("ldmatrix.sync.aligned.m8n8.x4.shared.b16 {%0,%1,%2,%3}, [%4];"
        : "=r"(r0), "=r"(r1), "=r"(r2), "=r"(r3) : "r"(addr));
}

__device__ __forceinline__ uint32_t smem_u32(const void* p) {
    uint32_t a;
    asm("{ .reg .u64 t; cvta.to.shared.u64 t, %1; cvt.u32.u64 %0, t; }"
        : "=r"(a) : "l"(p));
    return a;
}

// ---------------------------------------------------------------------------
// Split-bf16 GEMM on tensor cores (acc = Ah*Bh + Ah*Bl + Al*Bh).
// Tile TM x TN (templated), BK=32, 256 threads, 8 warps as 2M x 4N.
// grid: (nmat * tilesN, rows/TM, batch).   [R11 version — fp32 B, in-kernel split]
// ---------------------------------------------------------------------------
#define BK 32
#define AST 40
#define ASTB (AST * 2)

template <int TM, int TN, bool ACC>
__global__ __launch_bounds__(256, 2)
void mma_gemm_kernel(const float* __restrict__ A, long long aBatch,
                     const float* __restrict__ B0, const float* __restrict__ B1,
                     const float* __restrict__ B2,
                     float* __restrict__ C0, float* __restrict__ C1, float* __restrict__ C2,
                     long long cB0, long long cB1, long long cB2,
                     int K, int N, int tilesN)
{
    constexpr int WM = TM / 2;
    constexpr int WN = TN / 4;
    constexpr int MT = WM / 16;
    constexpr int NT = WN / 8;
    constexpr int P  = NT / 2;
    constexpr int A_HALF = TM * AST * 2;
    constexpr int B_HALF = TN * AST * 2;
    constexpr int CA  = TM / 32;
    constexpr int TPR = 256 / TM;
    constexpr int NB  = TN / 8;

    extern __shared__ char smem[];
    __nv_bfloat16* Ahi = (__nv_bfloat16*)smem;
    __nv_bfloat16* Alo = (__nv_bfloat16*)(smem + A_HALF);
    __nv_bfloat16* Bhi = (__nv_bfloat16*)(smem + 2 * A_HALF);
    __nv_bfloat16* Blo = (__nv_bfloat16*)(smem + 2 * A_HALF + B_HALF);

    const int tid = threadIdx.x;
    const int wid = tid >> 5, lane = tid & 31;
    const int wm = wid & 1, wn = wid >> 1;
    const int r  = lane >> 2, qc = (lane & 3) * 2;

    const int tn  = blockIdx.x % tilesN;
    const int mat = blockIdx.x / tilesN;
    const int bz  = blockIdx.z;
    const int m0  = blockIdx.y * TM;
    const int n0  = tn * TN;

    const float* Bm = (mat == 0) ? B0 : ((mat == 1) ? B1 : B2);
    float*       Cm = (mat == 0) ? C0 : ((mat == 1) ? C1 : C2);
    const long long cB = (mat == 0) ? cB0 : ((mat == 1) ? cB1 : cB2);

    const float* Ab = A + (long long)bz * aBatch + (long long)m0 * K;

    const uint32_t sAhi = smem_u32(Ahi);
    const uint32_t sBhi = smem_u32(Bhi);
    const uint32_t aLaneOff = (uint32_t)((lane & 15) * AST + (lane >> 4) * 8) * 2;
    const uint32_t bLaneOff = (uint32_t)((((lane & 7) + ((lane >> 4) << 3)) * AST
                                          + ((lane >> 3) & 1) * 8) * 2);

    const int ar  = tid / TPR,  akb = (tid % TPR) * (32 / TPR);
    const int bn  = tid % TN,   bkb = (tid / TN) * (TN / 8);

    float4 pa[CA];
    float  pb[NB];
    {
        const float* Ap = Ab + (size_t)ar * K + akb;
        #pragma unroll
        for (int j = 0; j < CA; j++) pa[j] = *(const float4*)(Ap + j * 4);
        const float* Bp = Bm + (size_t)bkb * N + n0 + bn;
        #pragma unroll
        for (int j = 0; j < NB; j++) pb[j] = Bp[(size_t)j * N];
    }

    float acc[MT][NT][4];
    #pragma unroll
    for (int i = 0; i < MT; i++)
        #pragma unroll
        for (int j = 0; j < NT; j++)
            #pragma unroll
            for (int e = 0; e < 4; e++) acc[i][j][e] = 0.f;

    const int NC = K / BK;
    #pragma unroll 1
    for (int kc = 0; kc < NC; kc++) {
        #pragma unroll
        for (int j = 0; j < CA; j++) {
            float4 v = pa[j];
            __nv_bfloat16 h0 = __float2bfloat16(v.x);
            __nv_bfloat16 h1 = __float2bfloat16(v.y);
            __nv_bfloat16 h2 = __float2bfloat16(v.z);
            __nv_bfloat16 h3 = __float2bfloat16(v.w);
            __nv_bfloat162 hp0 = __halves2bfloat162(h0, h1);
            __nv_bfloat162 hp1 = __halves2bfloat162(h2, h3);
            __nv_bfloat162 lp0 = __floats2bfloat162_rn(v.x - __bfloat162float(h0),
                                                       v.y - __bfloat162float(h1));
            __nv_bfloat162 lp1 = __floats2bfloat162_rn(v.z - __bfloat162float(h2),
                                                       v.w - __bfloat162float(h3));
            int off = ar * AST + akb + j * 4;
            *(uint2*)&Ahi[off] = make_uint2(*(uint32_t*)&hp0, *(uint32_t*)&hp1);
            *(uint2*)&Alo[off] = make_uint2(*(uint32_t*)&lp0, *(uint32_t*)&lp1);
        }
        #pragma unroll
        for (int g = 0; g < NB / 4; g++) {
            __nv_bfloat16 h0 = __float2bfloat16(pb[g * 4 + 0]);
            __nv_bfloat16 h1 = __float2bfloat16(pb[g * 4 + 1]);
            __nv_bfloat16 h2 = __float2bfloat16(pb[g * 4 + 2]);
            __nv_bfloat16 h3 = __float2bfloat16(pb[g * 4 + 3]);
            __nv_bfloat162 hp0 = __halves2bfloat162(h0, h1);
            __nv_bfloat162 hp1 = __halves2bfloat162(h2, h3);
            __nv_bfloat162 lp0 = __floats2bfloat162_rn(pb[g*4+0] - __bfloat162float(h0),
                                                       pb[g*4+1] - __bfloat162float(h1));
            __nv_bfloat162 lp1 = __floats2bfloat162_rn(pb[g*4+2] - __bfloat162float(h2),
                                                       pb[g*4+3] - __bfloat162float(h3));
            int off = bn * AST + bkb + g * 4;
            *(uint2*)&Bhi[off] = make_uint2(*(uint32_t*)&hp0, *(uint32_t*)&hp1);
            *(uint2*)&Blo[off] = make_uint2(*(uint32_t*)&lp0, *(uint32_t*)&lp1);
        }
        __syncthreads();

        if (kc + 1 < NC) {
            const int k0n = (kc + 1) * BK;
            const float* Ap = Ab + (size_t)ar * K + k0n + akb;
            #pragma unroll
            for (int j = 0; j < CA; j++) pa[j] = *(const float4*)(Ap + j * 4);
            const float* Bp = Bm + (size_t)(k0n + bkb) * N + n0 + bn;
            #pragma unroll
            for (int j = 0; j < NB; j++) pb[j] = Bp[(size_t)j * N];
        }

        #pragma unroll
        for (int ks = 0; ks < 2; ks++) {
            const uint32_t kOff = ks * 32;
            uint32_t bh[P][4], bl[P][4];
            #pragma unroll
            for (int p = 0; p < P; p++) {
                uint32_t baddr = sBhi + (uint32_t)(wn * WN + p * 16) * ASTB + kOff + bLaneOff;
                ldsm4(bh[p][0], bh[p][1], bh[p][2], bh[p][3], baddr);
                ldsm4(bl[p][0], bl[p][1], bl[p][2], bl[p][3], baddr + B_HALF);
            }
            #pragma unroll
            for (int mt = 0; mt < MT; mt++) {
                uint32_t aaddr = sAhi + (uint32_t)(wm * WM + mt * 16) * ASTB + kOff + aLaneOff;
                uint32_t ah0, ah1, ah2, ah3, al0, al1, al2, al3;
                ldsm4(ah0, ah1, ah2, ah3, aaddr);
                ldsm4(al0, al1, al2, al3, aaddr + A_HALF);
                #pragma unroll
                for (int nt = 0; nt < NT; nt++) {
                    uint32_t b0 = bh[nt >> 1][(nt & 1) * 2];
                    uint32_t b1 = bh[nt >> 1][(nt & 1) * 2 + 1];
                    uint32_t c0 = bl[nt >> 1][(nt & 1) * 2];
                    uint32_t c1 = bl[nt >> 1][(nt & 1) * 2 + 1];
                    mma16816(acc[mt][nt], ah0, ah1, ah2, ah3, b0, b1);
                    mma16816(acc[mt][nt], ah0, ah1, ah2, ah3, c0, c1);
                    mma16816(acc[mt][nt], al0, al1, al2, al3, b0, b1);
                }
            }
        }
        __syncthreads();
    }

    float* Cb = Cm + (long long)bz * cB;
    #pragma unroll
    for (int mt = 0; mt < MT; mt++) {
        int row0 = m0 + wm * WM + mt * 16 + r;
        #pragma unroll
        for (int nt = 0; nt < NT; nt++) {
            int col = n0 + wn * WN + nt * 8 + qc;
            float* p0 = Cb + (size_t)row0 * N + col;
            float* p1 = Cb + (size_t)(row0 + 8) * N + col;
            float2 v0 = make_float2(acc[mt][nt][0], acc[mt][nt][1]);
            float2 v1 = make_float2(acc[mt][nt][2], acc[mt][nt][3]);
            if (ACC) {
                float2 o0 = *(const float2*)p0;
                float2 o1 = *(const float2*)p1;
                v0.x += o0.x; v0.y += o0.y;
                v1.x += o1.x; v1.y += o1.y;
            }
            *(float2*)p0 = v0;
            *(float2*)p1 = v1;
        }
    }
}

#define SMEM_OF(TM, TN) (2 * (TM) * AST * 2 + 2 * (TN) * AST * 2)

// ---------------------------------------------------------------------------
// RMSNorm
// ---------------------------------------------------------------------------
__global__ __launch_bounds__(256)
void rmsnorm_kernel(const float* __restrict__ x, const float* __restrict__ w,
                    float* __restrict__ o)
{
    const int row = blockIdx.x;
    const int tid = threadIdx.x;
    const float4 v = *(const float4*)(x + (size_t)row * D_ + tid * 4);
    float ss = v.x * v.x + v.y * v.y + v.z * v.z + v.w * v.w;
    #pragma unroll
    for (int off = 16; off; off >>= 1)
        ss += __shfl_xor_sync(0xffffffffu, ss, off);
    __shared__ float ws[8];
    __shared__ float s_inv;
    if ((tid & 31) == 0) ws[tid >> 5] = ss;
    __syncthreads();
    if (tid == 0) {
        float t = 0.f;
        #pragma unroll
        for (int i = 0; i < 8; i++) t += ws[i];
        s_inv = rsqrtf(t * (1.0f / D_) + 1e-5f);
    }
    __syncthreads();
    const float inv = s_inv;
    const float4 wv = *(const float4*)(w + tid * 4);
    float4 ov;
    ov.x = v.x * inv * wv.x;
    ov.y = v.y * inv * wv.y;
    ov.z = v.z * inv * wv.z;
    ov.w = v.w * inv * wv.w;
    *(float4*)(o + (size_t)row * D_ + tid * 4) = ov;
}

// ---------------------------------------------------------------------------
// SwiGLU gate (float4)
// ---------------------------------------------------------------------------
__global__ void silu_gate_kernel(float4* __restrict__ t1,
                                 const float4* __restrict__ t3, int n4)
{
    int i = blockIdx.x * blockDim.x + threadIdx.x;
    if (i < n4) {
        float4 a = t1[i];
        float4 b = t3[i];
        float4 o;
        o.x = (a.x / (1.f + __expf(-a.x))) * b.x;
        o.y = (a.y / (1.f + __expf(-a.y))) * b.y;
        o.z = (a.z / (1.f + __expf(-a.z))) * b.z;
        o.w = (a.w / (1.f + __expf(-a.w))) * b.w;
        t1[i] = o;
    }
}

// ---------------------------------------------------------------------------
// RoPE
// ---------------------------------------------------------------------------
__global__ void rope_kernel(float* __restrict__ t,
                            const float* __restrict__ cosT,
                            const float* __restrict__ sinT,
                            int rowsMod, int posOff, int nPairs)
{
    int id = blockIdx.x * blockDim.x + threadIdx.x;
    if (id >= nPairs) return;
    int pair = id & 511;
    int row  = id >> 9;
    int pos  = posOff + (row % rowsMod);
    int i    = pair & 31;
    float c = cosT[pos * 32 + i];
    float s = sinT[pos * 32 + i];
    float2* p = (float2*)(t + (size_t)row * D_ + pair * 2);
    float2 v = *p;
    float2 o;
    o.x = v.x * c - v.y * s;
    o.y = v.x * s + v.y * c;
    *p = o;
}

// ---------------------------------------------------------------------------
// Tensor-core flash attention (split-bf16, x-part queries only).
// 64q x 64k tiles, HD=64. 256 threads, 8 warps (2q x 4n).
// ---------------------------------------------------------------------------
#define QST  72
#define QSTB (QST * 2)
#define PLANE (64 * QST * 2)           // 9216 bytes per bf16 plane
#define AOFF_QH 0
#define AOFF_QL (1 * PLANE)
#define AOFF_KH (2 * PLANE)
#define AOFF_KL (3 * PLANE)
#define AOFF_PH (4 * PLANE)
#define AOFF_PL (5 * PLANE)
#define AOFF_VH (6 * PLANE)
#define AOFF_VL (7 * PLANE)
#define AOFF_SS (8 * PLANE)            // fp32 64 x SST
#define SST 66
#define AOFF_M  (AOFF_SS + 64 * SST * 4)
#define AOFF_L  (AOFF_M + 256)
#define AOFF_C  (AOFF_L + 256)
#define ATTN_SMEM2 (AOFF_C + 256)

__device__ __forceinline__ void split_store4(char* base, int elemOff, float4 v)
{
    __nv_bfloat16 h0 = __float2bfloat16(v.x);
    __nv_bfloat16 h1 = __float2bfloat16(v.y);
    __nv_bfloat16 h2 = __float2bfloat16(v.z);
    __nv_bfloat16 h3 = __float2bfloat16(v.w);
    __nv_bfloat162 hp0 = __halves2bfloat162(h0, h1);
    __nv_bfloat162 hp1 = __halves2bfloat162(h2, h3);
    __nv_bfloat162 lp0 = __floats2bfloat162_rn(v.x - __bfloat162float(h0),
                                               v.y - __bfloat162float(h1));
    __nv_bfloat162 lp1 = __floats2bfloat162_rn(v.z - __bfloat162float(h2),
                                               v.w - __bfloat162float(h3));
    *(uint2*)(base + elemOff * 2) = make_uint2(*(uint32_t*)&hp0, *(uint32_t*)&hp1);
    *(uint2*)(base + PLANE + elemOff * 2) = make_uint2(*(uint32_t*)&lp0, *(uint32_t*)&lp1);
}

__global__ __launch_bounds__(256, 2)
void attn_mma_kernel(const float* __restrict__ Qx,
                     const float* __restrict__ Km, const float* __restrict__ Vm,
                     const float* __restrict__ Kx, const float* __restrict__ Vx,
                     float* __restrict__ Out, int sBase)
{
    extern __shared__ char sm[];
    float* Ss   = (float*)(sm + AOFF_SS);
    float* mrow = (float*)(sm + AOFF_M);
    float* lrow = (float*)(sm + AOFF_L);
    float* crow = (float*)(sm + AOFF_C);

    const int b  = blockIdx.z;
    const int h  = blockIdx.y;
    const int qt = blockIdx.x;
    const int tid = threadIdx.x;
    const int wid = tid >> 5, lane = tid & 31;
    const int wm = wid & 1, wn = wid >> 1;
    const int r  = lane >> 2, qc = (lane & 3) * 2;
    const int q0 = qt * 64;

    const uint32_t sbase = smem_u32(sm);
    const uint32_t aLaneOff = (uint32_t)((lane & 15) * QST + (lane >> 4) * 8) * 2;
    const uint32_t bLaneOff = (uint32_t)((((lane & 7) + ((lane >> 4) << 3)) * QST
                                          + ((lane >> 3) & 1) * 8) * 2);

    // --- Load Q tile (split to bf16 hi/lo): row j, 16 d per thread ---
    {
        const int j = tid >> 2, dq = (tid & 3) * 16;
        const float* Qp = &Qx[((size_t)(b * S_ + sBase + q0 + j)) * D_ + h * HD_ + dq];
        #pragma unroll
        for (int i = 0; i < 4; i++)
            split_store4(sm + AOFF_QH, j * QST + dq + i * 4, *(const float4*)(Qp + i * 4));
    }
    if (tid < 64) { mrow[tid] = -1e30f; lrow[tid] = 0.f; }

    float acc[2][2][4];
    #pragma unroll
    for (int i = 0; i < 2; i++)
        #pragma unroll
        for (int j = 0; j < 2; j++)
            #pragma unroll
            for (int e = 0; e < 4; e++) acc[i][j][e] = 0.f;
    __syncthreads();

    const int nkt = qt + 9;
    #pragma unroll 1
    for (int kt = 0; kt < nkt; kt++) {
        const float* Kp;
        const float* Vp;
        size_t rb;
        if (kt < 8) { Kp = Km; Vp = Vm; rb = (size_t)(b * M_ + kt * 64); }
        else        { Kp = Kx; Vp = Vx; rb = (size_t)(b * S_ + sBase + (kt - 8) * 64); }

        // K tile: row j (kpos), 16 d per thread  -> Ks[j][d]
        {
            const int j = tid >> 2, dq = (tid & 3) * 16;
            const float* kp = &Kp[(rb + j) * D_ + h * HD_ + dq];
            #pragma unroll
            for (int i = 0; i < 4; i++)
                split_store4(sm + AOFF_KH, j * QST + dq + i * 4, *(const float4*)(kp + i * 4));
        }
        // V tile transposed: thread owns kpos=tid&63, 16 d -> Vt[d][kpos]
        {
            const int kp = tid & 63, db = (tid >> 6) * 16;
            const float* vp = &Vp[(rb + kp) * D_ + h * HD_ + db];
            #pragma unroll
            for (int i = 0; i < 4; i++) {
                float4 v = *(const float4*)(vp + i * 4);
                float vv[4] = {v.x, v.y, v.z, v.w};
                #pragma unroll
                for (int e = 0; e < 4; e++) {
                    int d = db + i * 4 + e;
                    __nv_bfloat16 hh = __float2bfloat16(vv[e]);
                    *(__nv_bfloat16*)(sm + AOFF_VH + (d * QST + kp) * 2) = hh;
                    *(__nv_bfloat16*)(sm + AOFF_VL + (d * QST + kp) * 2) =
                        __float2bfloat16(vv[e] - __bfloat162float(hh));
                }
            }
        }
        __syncthreads();

        // --- S = Q @ K^T (split, 4 k-steps over d) ---
        float s[2][2][4];
        #pragma unroll
        for (int i = 0; i < 2; i++)
            #pragma unroll
            for (int j = 0; j < 2; j++)
                #pragma unroll
                for (int e = 0; e < 4; e++) s[i][j][e] = 0.f;
        #pragma unroll
        for (int ks = 0; ks < 4; ks++) {
            const uint32_t kOff = ks * 32;
            uint32_t bh[4], bl[4];
            uint32_t baddr = sbase + AOFF_KH + (uint32_t)(wn * 16) * QSTB + kOff + bLaneOff;
            ldsm4(bh[0], bh[1], bh[2], bh[3], baddr);
            ldsm4(bl[0], bl[1], bl[2], bl[3], baddr + PLANE);
            #pragma unroll
            for (int mt = 0; mt < 2; mt++) {
                uint32_t aaddr = sbase + AOFF_QH + (uint32_t)(wm * 32 + mt * 16) * QSTB + kOff + aLaneOff;
                uint32_t ah0, ah1, ah2, ah3, al0, al1, al2, al3;
                ldsm4(ah0, ah1, ah2, ah3, aaddr);
                ldsm4(al0, al1, al2, al3, aaddr + PLANE);
                #pragma unroll
                for (int nt = 0; nt < 2; nt++) {
                    uint32_t b0 = bh[nt * 2], b1 = bh[nt * 2 + 1];
                    uint32_t c0 = bl[nt * 2], c1 = bl[nt * 2 + 1];
                    mma16816(s[mt][nt], ah0, ah1, ah2, ah3, b0, b1);
                    mma16816(s[mt][nt], ah0, ah1, ah2, ah3, c0, c1);
                    mma16816(s[mt][nt], al0, al1, al2, al3, b0, b1);
                }
            }
        }
        // scale + causal mask -> Ss
        #pragma unroll
        for (int mt = 0; mt < 2; mt++) {
            int row0 = wm * 32 + mt * 16 + r;
            int qi0 = M_ + q0 + row0, qi1 = qi0 + 8;
            #pragma unroll
            for (int nt = 0; nt < 2; nt++) {
                int col = wn * 16 + nt * 8 + qc;
                int kj = kt * 64 + col;
                Ss[row0 * SST + col]           = (kj     <= qi0) ? s[mt][nt][0] * 0.125f : -1e30f;
                Ss[row0 * SST + col + 1]       = (kj + 1 <= qi0) ? s[mt][nt][1] * 0.125f : -1e30f;
                Ss[(row0 + 8) * SST + col]     = (kj     <= qi1) ? s[mt][nt][2] * 0.125f : -1e30f;
                Ss[(row0 + 8) * SST + col + 1] = (kj + 1 <= qi1) ? s[mt][nt][3] * 0.125f : -1e30f;
            }
        }
        __syncthreads();

        // --- softmax: 4 threads per row, 16 cols each ---
        {
            const int row = tid >> 2, part = tid & 3;
            float p[16];
            float mx = -1e30f;
            #pragma unroll
            for (int j = 0; j < 16; j++) {
                p[j] = Ss[row * SST + part * 16 + j];
                mx = fmaxf(mx, p[j]);
            }
            mx = fmaxf(mx, __shfl_xor_sync(0xffffffffu, mx, 1));
            mx = fmaxf(mx, __shfl_xor_sync(0xffffffffu, mx, 2));
            float mold = mrow[row];
            float mnew = fmaxf(mold, mx);
            float sum = 0.f;
            #pragma unroll
            for (int j = 0; j < 16; j++) {
                p[j] = __expf(p[j] - mnew);
                sum += p[j];
            }
            sum += __shfl_xor_sync(0xffffffffu, sum, 1);
            sum += __shfl_xor_sync(0xffffffffu, sum, 2);
            if (part == 0) {
                float c = __expf(mold - mnew);
                mrow[row] = mnew;
                lrow[row] = lrow[row] * c + sum;
                crow[row] = c;
            }
            // write P planes (bf16 hi/lo pairs)
            #pragma unroll
            for (int j = 0; j < 8; j++) {
                float v0 = p[j * 2], v1 = p[j * 2 + 1];
                __nv_bfloat16 h0 = __float2bfloat16(v0);
                __nv_bfloat16 h1 = __float2bfloat16(v1);
                __nv_bfloat162 hp = __halves2bfloat162(h0, h1);
                __nv_bfloat162 lp = __floats2bfloat162_rn(v0 - __bfloat162float(h0),
                                                          v1 - __bfloat162float(h1));
                int off = (row * QST + part * 16 + j * 2) * 2;
                *(uint32_t*)(sm + AOFF_PH + off) = *(uint32_t*)&hp;
                *(uint32_t*)(sm + AOFF_PL + off) = *(uint32_t*)&lp;
            }
        }
        __syncthreads();

        // --- rescale acc, then O += P @ V (split, 4 k-steps over kpos) ---
        #pragma unroll
        for (int mt = 0; mt < 2; mt++) {
            int row0 = wm * 32 + mt * 16 + r;
            float c0 = crow[row0], c1 = crow[row0 + 8];
            #pragma unroll
            for (int nt = 0; nt < 2; nt++) {
                acc[mt][nt][0] *= c0; acc[mt][nt][1] *= c0;
                acc[mt][nt][2] *= c1; acc[mt][nt][3] *= c1;
            }
        }
        #pragma unroll
        for (int ks = 0; ks < 4; ks++) {
            const uint32_t kOff = ks * 32;
            uint32_t bh[4], bl[4];
            uint32_t baddr = sbase + AOFF_VH + (uint32_t)(wn * 16) * QSTB + kOff + bLaneOff;
            ldsm4(bh[0], bh[1], bh[2], bh[3], baddr);
            ldsm4(bl[0], bl[1], bl[2], bl[3], baddr + PLANE);
            #pragma unroll
            for (int mt = 0; mt < 2; mt++) {
                uint32_t aaddr = sbase + AOFF_PH + (uint32_t)(wm * 32 + mt * 16) * QSTB + kOff + aLaneOff;
                uint32_t ph0, ph1, ph2, ph3, pl0, pl1, pl2, pl3;
                ldsm4(ph0, ph1, ph2, ph3, aaddr);
                ldsm4(pl0, pl1, pl2, pl3, aaddr + PLANE);
                #pragma unroll
                for (int nt = 0; nt < 2; nt++) {
                    uint32_t b0 = bh[nt * 2], b1 = bh[nt * 2 + 1];
                    uint32_t c0 = bl[nt * 2], c1 = bl[nt * 2 + 1];
                    mma16816(acc[mt][nt], ph0, ph1, ph2, ph3, b0, b1);
                    mma16816(acc[mt][nt], ph0, ph1, ph2, ph3, c0, c1);
                    mma16816(acc[mt][nt], pl0, pl1, pl2, pl3, b0, b1);
                }
            }
        }
        __syncthreads();
    }

    // --- epilogue: divide by l, write out ---
    #pragma unroll
    for (int mt = 0; mt < 2; mt++) {
        int row0 = wm * 32 + mt * 16 + r;
        float inv0 = 1.f / lrow[row0];
        float inv1 = 1.f / lrow[row0 + 8];
        int g0 = b * S_ + sBase + q0 + row0;
        #pragma unroll
        for (int nt = 0; nt < 2; nt++) {
            int col = wn * 16 + nt * 8 + qc;
            *(float2*)&Out[(size_t)g0 * D_ + h * HD_ + col] =
                make_float2(acc[mt][nt][0] * inv0, acc[mt][nt][1] * inv0);
            *(float2*)&Out[(size_t)(g0 + 8) * D_ + h * HD_ + col] =
                make_float2(acc[mt][nt][2] * inv1, acc[mt][nt][3] * inv1);
        }
    }
}

// ---------------------------------------------------------------------------
// Launch
// ---------------------------------------------------------------------------
extern "C" void kernel_launch(void* const* d_in, const int* in_sizes, int n_in,
                              void* d_out, int out_size)
{
    const float* x        = (const float*)d_in[0];
    const float* cosT     = (const float*)d_in[1];
    const float* sinT     = (const float*)d_in[2];
    const float* wq       = (const float*)d_in[3];
    const float* wk       = (const float*)d_in[4];
    const float* wv       = (const float*)d_in[5];
    const float* wo       = (const float*)d_in[6];
    const float* wm       = (const float*)d_in[7];
    const float* wkm      = (const float*)d_in[8];
    const float* wvm      = (const float*)d_in[9];
    const float* w1       = (const float*)d_in[10];
    const float* w3       = (const float*)d_in[11];
    const float* w2       = (const float*)d_in[12];
    const float* ffn_nw   = (const float*)d_in[13];
    const float* mem_nw   = (const float*)d_in[14];
    const float* omem     = (const float*)d_in[15];
    float* out = (float*)d_out;

    float *p_allout, *p_qx, *p_kx, *p_vx, *p_a, *p_hn, *p_t1, *p_t3, *p_m2, *p_k, *p_v;
    cudaGetSymbolAddress((void**)&p_allout, g_allout);
    cudaGetSymbolAddress((void**)&p_qx, g_qx);
    cudaGetSymbolAddress((void**)&p_kx, g_kx);
    cudaGetSymbolAddress((void**)&p_vx, g_vx);
    cudaGetSymbolAddress((void**)&p_a,  g_a);
    cudaGetSymbolAddress((void**)&p_hn, g_hn);
    cudaGetSymbolAddress((void**)&p_t1, g_t1);
    cudaGetSymbolAddress((void**)&p_t3, g_t3);
    cudaGetSymbolAddress((void**)&p_m2, g_m2);
    cudaGetSymbolAddress((void**)&p_k,  g_k);
    cudaGetSymbolAddress((void**)&p_v,  g_v);

    cudaFuncSetAttribute(attn_mma_kernel,
                         cudaFuncAttributeMaxDynamicSharedMemorySize, ATTN_SMEM2);

    const long long MD  = (long long)M_ * D_;
    const long long MH  = (long long)M_ * HID_;
    const long long SD  = (long long)S_ * D_;

    // ---- Upfront: all-step QKV projections + RoPE ----
    mma_gemm_kernel<128, 128, false><<<dim3(24, 32, 2), 256, SMEM_OF(128, 128)>>>(
        x, SD, wq, wk, wv, p_qx, p_kx, p_vx, SD, SD, SD, D_, D_, 8);
    {
        int n = B_ * S_ * (D_ / 2);
        rope_kernel<<<(n + 255) / 256, 256>>>(p_qx, cosT, sinT, 512, M_, n);
        rope_kernel<<<(n + 255) / 256, 256>>>(p_kx, cosT, sinT, 512, M_, n);
    }

    // ---- Sequential memory chain ----
    for (int s = 0; s < NSTEP; s++) {
        const float* om = (s == 0) ? omem : (p_allout + (size_t)(s - 1) * M_ * D_);
        const long long omB = (s == 0) ? 0LL : SD;

        mma_gemm_kernel<64, 64, false><<<dim3(16, 8, 2), 256, SMEM_OF(64, 64)>>>(
            om, omB, wm, wm, wm, p_a, p_a, p_a, MD, MD, MD, D_, D_, 16);
        rmsnorm_kernel<<<B_ * M_, 256>>>(p_a, ffn_nw, p_hn);
        mma_gemm_kernel<64, 128, false><<<dim3(44, 8, 2), 256, SMEM_OF(64, 128)>>>(
            p_hn, MD, w1, w3, w3, p_t1, p_t3, p_t3, MH, MH, MH, D_, HID_, 22);
        silu_gate_kernel<<<(B_ * M_ * HID_ / 4 + 255) / 256, 256>>>(
            (float4*)p_t1, (const float4*)p_t3, B_ * M_ * HID_ / 4);
        mma_gemm_kernel<64, 64, true><<<dim3(16, 8, 2), 256, SMEM_OF(64, 64)>>>(
            p_t1, MH, w2, w2, w2, p_a, p_a, p_a, MD, MD, MD, HID_, D_, 16);
        rmsnorm_kernel<<<B_ * M_, 256>>>(p_a, mem_nw, p_m2);
        mma_gemm_kernel<64, 128, false><<<dim3(16, 8, 2), 256, SMEM_OF(64, 128)>>>(
            p_m2, MD, wkm, wvm, wvm, p_k, p_v, p_v, MD, MD, MD, D_, D_, 8);
        {
            int n = B_ * M_ * (D_ / 2);
            rope_kernel<<<(n + 255) / 256, 256>>>(p_k, cosT, sinT, 512, 0, n);
        }
        attn_mma_kernel<<<dim3(M_ / 64, H_, B_), 256, ATTN_SMEM2>>>(
            p_qx, p_k, p_v, p_kx, p_vx, p_allout, s * M_);
    }

    // out = allout @ wo
    mma_gemm_kernel<128, 128, false><<<dim3(8, 64, 1), 256, SMEM_OF(128, 128)>>>(
        p_allout, 0LL, wo, wo, wo, out, out, out, 0LL, 0LL, 0LL, D_, D_, 8);
}

// round 15
// speedup vs baseline: 1.3303x; 1.0103x over previous
#include <cuda_runtime.h>
#include <cuda_bf16.h>
#include <cstdint>
#include <math.h>

// Problem constants
#define B_  2
#define S_  4096
#define D_  1024
#define H_  16
#define HD_ 64
#define M_  512
#define L_  1024
#define HID_ 2816
#define NSTEP 8

// ---------------------------------------------------------------------------
// Scratch (device globals; no allocation allowed)
// ---------------------------------------------------------------------------
__device__ float g_allout[B_ * S_ * D_];
__device__ float g_qx[B_ * S_ * D_];
__device__ float g_kx[B_ * S_ * D_];
__device__ float g_vx[B_ * S_ * D_];
__device__ float g_a  [B_ * M_ * D_];
__device__ float g_hn [B_ * M_ * D_];
__device__ float g_t1 [B_ * M_ * HID_];
__device__ float g_t3 [B_ * M_ * HID_];
__device__ float g_m2 [B_ * M_ * D_];
__device__ float g_k  [B_ * M_ * D_];      // mem-part K (UNroped; rope fused in attn)
__device__ float g_v  [B_ * M_ * D_];

// ---------------------------------------------------------------------------
// Warp-level bf16 MMA + ldmatrix helpers (valid under compute_103 target)
// ---------------------------------------------------------------------------
__device__ __forceinline__ void mma16816(float* c,
                                         uint32_t a0, uint32_t a1, uint32_t a2, uint32_t a3,
                                         uint32_t b0, uint32_t b1)
{
    asm volatile(
        "mma.sync.aligned.m16n8k16.row.col.f32.bf16.bf16.f32 "
        "{%0,%1,%2,%3}, {%4,%5,%6,%7}, {%8,%9}, {%0,%1,%2,%3};"
        : "+f"(c[0]), "+f"(c[1]), "+f"(c[2]), "+f"(c[3])
        : "r"(a0), "r"(a1), "r"(a2), "r"(a3), "r"(b0), "r"(b1));
}

__device__ __forceinline__ void ldsm4(uint32_t& r0, uint32_t& r1,
                                      uint32_t& r2, uint32_t& r3, uint32_t addr)
{
    asm volatile("ldmatrix.sync.aligned.m8n8.x4.shared.b16 {%0,%1,%2,%3}, [%4];"
        : "=r"(r0), "=r"(r1), "=r"(r2), "=r"(r3) : "r"(addr));
}

__device__ __forceinline__ uint32_t smem_u32(const void* p) {
    uint32_t a;
    asm("{ .reg .u64 t; cvta.to.shared.u64 t, %1; cvt.u32.u64 %0, t; }"
        : "=r"(a) : "l"(p));
    return a;
}

// ---------------------------------------------------------------------------
// Split-bf16 GEMM on tensor cores (acc = Ah*Bh + Ah*Bl + Al*Bh).
// Tile TM x TN, BK=32, 256 threads, 8 warps as 2M x 4N.
// Double-buffered smem: one __syncthreads per K-chunk.
// grid: (nmat * tilesN, rows/TM, batch).
// ---------------------------------------------------------------------------
#define BK 32
#define AST 40
#define ASTB (AST * 2)

template <int TM, int TN, bool ACC>
__global__ __launch_bounds__(256, 2)
void mma_gemm_kernel(const float* __restrict__ A, long long aBatch,
                     const float* __restrict__ B0, const float* __restrict__ B1,
                     const float* __restrict__ B2,
                     float* __restrict__ C0, float* __restrict__ C1, float* __restrict__ C2,
                     long long cB0, long long cB1, long long cB2,
                     int K, int N, int tilesN)
{
    constexpr int WM = TM / 2;
    constexpr int WN = TN / 4;
    constexpr int MT = WM / 16;
    constexpr int NT = WN / 8;
    constexpr int P  = NT / 2;
    constexpr int A_HALF = TM * AST * 2;
    constexpr int B_HALF = TN * AST * 2;
    constexpr int SSZ = 2 * A_HALF + 2 * B_HALF;   // one stage
    constexpr int CA  = TM / 32;
    constexpr int TPR = 256 / TM;
    constexpr int NB  = TN / 8;

    extern __shared__ char smem[];

    const int tid = threadIdx.x;
    const int wid = tid >> 5, lane = tid & 31;
    const int wm = wid & 1, wn = wid >> 1;
    const int r  = lane >> 2, qc = (lane & 3) * 2;

    const int tn  = blockIdx.x % tilesN;
    const int mat = blockIdx.x / tilesN;
    const int bz  = blockIdx.z;
    const int m0  = blockIdx.y * TM;
    const int n0  = tn * TN;

    const float* Bm = (mat == 0) ? B0 : ((mat == 1) ? B1 : B2);
    float*       Cm = (mat == 0) ? C0 : ((mat == 1) ? C1 : C2);
    const long long cB = (mat == 0) ? cB0 : ((mat == 1) ? cB1 : cB2);

    const float* Ab = A + (long long)bz * aBatch + (long long)m0 * K;

    const uint32_t sbase = smem_u32(smem);
    const uint32_t aLaneOff = (uint32_t)((lane & 15) * AST + (lane >> 4) * 8) * 2;
    const uint32_t bLaneOff = (uint32_t)((((lane & 7) + ((lane >> 4) << 3)) * AST
                                          + ((lane >> 3) & 1) * 8) * 2);

    const int ar  = tid / TPR,  akb = (tid % TPR) * (32 / TPR);
    const int bn  = tid % TN,   bkb = (tid / TN) * (TN / 8);

    float4 pa[CA];
    float  pb[NB];

    auto cvt_store = [&](char* stg) {
        __nv_bfloat16* Ahi = (__nv_bfloat16*)stg;
        __nv_bfloat16* Alo = (__nv_bfloat16*)(stg + A_HALF);
        __nv_bfloat16* Bhi = (__nv_bfloat16*)(stg + 2 * A_HALF);
        __nv_bfloat16* Blo = (__nv_bfloat16*)(stg + 2 * A_HALF + B_HALF);
        #pragma unroll
        for (int j = 0; j < CA; j++) {
            float4 v = pa[j];
            __nv_bfloat16 h0 = __float2bfloat16(v.x);
            __nv_bfloat16 h1 = __float2bfloat16(v.y);
            __nv_bfloat16 h2 = __float2bfloat16(v.z);
            __nv_bfloat16 h3 = __float2bfloat16(v.w);
            __nv_bfloat162 hp0 = __halves2bfloat162(h0, h1);
            __nv_bfloat162 hp1 = __halves2bfloat162(h2, h3);
            __nv_bfloat162 lp0 = __floats2bfloat162_rn(v.x - __bfloat162float(h0),
                                                       v.y - __bfloat162float(h1));
            __nv_bfloat162 lp1 = __floats2bfloat162_rn(v.z - __bfloat162float(h2),
                                                       v.w - __bfloat162float(h3));
            int off = ar * AST + akb + j * 4;
            *(uint2*)&Ahi[off] = make_uint2(*(uint32_t*)&hp0, *(uint32_t*)&hp1);
            *(uint2*)&Alo[off] = make_uint2(*(uint32_t*)&lp0, *(uint32_t*)&lp1);
        }
        #pragma unroll
        for (int g = 0; g < NB / 4; g++) {
            __nv_bfloat16 h0 = __float2bfloat16(pb[g * 4 + 0]);
            __nv_bfloat16 h1 = __float2bfloat16(pb[g * 4 + 1]);
            __nv_bfloat16 h2 = __float2bfloat16(pb[g * 4 + 2]);
            __nv_bfloat16 h3 = __float2bfloat16(pb[g * 4 + 3]);
            __nv_bfloat162 hp0 = __halves2bfloat162(h0, h1);
            __nv_bfloat162 hp1 = __halves2bfloat162(h2, h3);
            __nv_bfloat162 lp0 = __floats2bfloat162_rn(pb[g*4+0] - __bfloat162float(h0),
                                                       pb[g*4+1] - __bfloat162float(h1));
            __nv_bfloat162 lp1 = __floats2bfloat162_rn(pb[g*4+2] - __bfloat162float(h2),
                                                       pb[g*4+3] - __bfloat162float(h3));
            int off = bn * AST + bkb + g * 4;
            *(uint2*)&Bhi[off] = make_uint2(*(uint32_t*)&hp0, *(uint32_t*)&hp1);
            *(uint2*)&Blo[off] = make_uint2(*(uint32_t*)&lp0, *(uint32_t*)&lp1);
        }
    };

    // Preload + stage chunk 0
    {
        const float* Ap = Ab + (size_t)ar * K + akb;
        #pragma unroll
        for (int j = 0; j < CA; j++) pa[j] = *(const float4*)(Ap + j * 4);
        const float* Bp = Bm + (size_t)bkb * N + n0 + bn;
        #pragma unroll
        for (int j = 0; j < NB; j++) pb[j] = Bp[(size_t)j * N];
    }
    cvt_store(smem);
    __syncthreads();

    float acc[MT][NT][4];
    #pragma unroll
    for (int i = 0; i < MT; i++)
        #pragma unroll
        for (int j = 0; j < NT; j++)
            #pragma unroll
            for (int e = 0; e < 4; e++) acc[i][j][e] = 0.f;

    const int NC = K / BK;
    #pragma unroll 1
    for (int kc = 0; kc < NC; kc++) {
        // issue global loads for chunk kc+1 (latency hidden by MMA below)
        if (kc + 1 < NC) {
            const int k0n = (kc + 1) * BK;
            const float* Ap = Ab + (size_t)ar * K + k0n + akb;
            #pragma unroll
            for (int j = 0; j < CA; j++) pa[j] = *(const float4*)(Ap + j * 4);
            const float* Bp = Bm + (size_t)(k0n + bkb) * N + n0 + bn;
            #pragma unroll
            for (int j = 0; j < NB; j++) pb[j] = Bp[(size_t)j * N];
        }

        // MMA from stage kc&1
        const uint32_t aPlane = sbase + (uint32_t)((kc & 1) * SSZ);
        const uint32_t bPlane = aPlane + 2 * A_HALF;
        #pragma unroll
        for (int ks = 0; ks < 2; ks++) {
            const uint32_t kOff = ks * 32;
            uint32_t bh[P][4], bl[P][4];
            #pragma unroll
            for (int p = 0; p < P; p++) {
                uint32_t baddr = bPlane + (uint32_t)(wn * WN + p * 16) * ASTB + kOff + bLaneOff;
                ldsm4(bh[p][0], bh[p][1], bh[p][2], bh[p][3], baddr);
                ldsm4(bl[p][0], bl[p][1], bl[p][2], bl[p][3], baddr + B_HALF);
            }
            #pragma unroll
            for (int mt = 0; mt < MT; mt++) {
                uint32_t aaddr = aPlane + (uint32_t)(wm * WM + mt * 16) * ASTB + kOff + aLaneOff;
                uint32_t ah0, ah1, ah2, ah3, al0, al1, al2, al3;
                ldsm4(ah0, ah1, ah2, ah3, aaddr);
                ldsm4(al0, al1, al2, al3, aaddr + A_HALF);
                #pragma unroll
                for (int nt = 0; nt < NT; nt++) {
                    uint32_t b0 = bh[nt >> 1][(nt & 1) * 2];
                    uint32_t b1 = bh[nt >> 1][(nt & 1) * 2 + 1];
                    uint32_t c0 = bl[nt >> 1][(nt & 1) * 2];
                    uint32_t c1 = bl[nt >> 1][(nt & 1) * 2 + 1];
                    mma16816(acc[mt][nt], ah0, ah1, ah2, ah3, b0, b1);
                    mma16816(acc[mt][nt], ah0, ah1, ah2, ah3, c0, c1);
                    mma16816(acc[mt][nt], al0, al1, al2, al3, b0, b1);
                }
            }
        }

        // stage chunk kc+1 into the other buffer
        if (kc + 1 < NC)
            cvt_store(smem + ((kc + 1) & 1) * SSZ);
        __syncthreads();
    }

    float* Cb = Cm + (long long)bz * cB;
    #pragma unroll
    for (int mt = 0; mt < MT; mt++) {
        int row0 = m0 + wm * WM + mt * 16 + r;
        #pragma unroll
        for (int nt = 0; nt < NT; nt++) {
            int col = n0 + wn * WN + nt * 8 + qc;
            float* p0 = Cb + (size_t)row0 * N + col;
            float* p1 = Cb + (size_t)(row0 + 8) * N + col;
            float2 v0 = make_float2(acc[mt][nt][0], acc[mt][nt][1]);
            float2 v1 = make_float2(acc[mt][nt][2], acc[mt][nt][3]);
            if (ACC) {
                float2 o0 = *(const float2*)p0;
                float2 o1 = *(const float2*)p1;
                v0.x += o0.x; v0.y += o0.y;
                v1.x += o1.x; v1.y += o1.y;
            }
            *(float2*)p0 = v0;
            *(float2*)p1 = v1;
        }
    }
}

#define SMEM_OF(TM, TN) (2 * (2 * (TM) * AST * 2 + 2 * (TN) * AST * 2))

// ---------------------------------------------------------------------------
// RMSNorm
// ---------------------------------------------------------------------------
__global__ __launch_bounds__(256)
void rmsnorm_kernel(const float* __restrict__ x, const float* __restrict__ w,
                    float* __restrict__ o)
{
    const int row = blockIdx.x;
    const int tid = threadIdx.x;
    const float4 v = *(const float4*)(x + (size_t)row * D_ + tid * 4);
    float ss = v.x * v.x + v.y * v.y + v.z * v.z + v.w * v.w;
    #pragma unroll
    for (int off = 16; off; off >>= 1)
        ss += __shfl_xor_sync(0xffffffffu, ss, off);
    __shared__ float ws[8];
    __shared__ float s_inv;
    if ((tid & 31) == 0) ws[tid >> 5] = ss;
    __syncthreads();
    if (tid == 0) {
        float t = 0.f;
        #pragma unroll
        for (int i = 0; i < 8; i++) t += ws[i];
        s_inv = rsqrtf(t * (1.0f / D_) + 1e-5f);
    }
    __syncthreads();
    const float inv = s_inv;
    const float4 wv = *(const float4*)(w + tid * 4);
    float4 ov;
    ov.x = v.x * inv * wv.x;
    ov.y = v.y * inv * wv.y;
    ov.z = v.z * inv * wv.z;
    ov.w = v.w * inv * wv.w;
    *(float4*)(o + (size_t)row * D_ + tid * 4) = ov;
}

// ---------------------------------------------------------------------------
// SwiGLU gate (float4)
// ---------------------------------------------------------------------------
__global__ void silu_gate_kernel(float4* __restrict__ t1,
                                 const float4* __restrict__ t3, int n4)
{
    int i = blockIdx.x * blockDim.x + threadIdx.x;
    if (i < n4) {
        float4 a = t1[i];
        float4 b = t3[i];
        float4 o;
        o.x = (a.x / (1.f + __expf(-a.x))) * b.x;
        o.y = (a.y / (1.f + __expf(-a.y))) * b.y;
        o.z = (a.z / (1.f + __expf(-a.z))) * b.z;
        o.w = (a.w / (1.f + __expf(-a.w))) * b.w;
        t1[i] = o;
    }
}

// ---------------------------------------------------------------------------
// RoPE (upfront only: qx, kx)
// ---------------------------------------------------------------------------
__global__ void rope_kernel(float* __restrict__ t,
                            const float* __restrict__ cosT,
                            const float* __restrict__ sinT,
                            int rowsMod, int posOff, int nPairs)
{
    int id = blockIdx.x * blockDim.x + threadIdx.x;
    if (id >= nPairs) return;
    int pair = id & 511;
    int row  = id >> 9;
    int pos  = posOff + (row % rowsMod);
    int i    = pair & 31;
    float c = cosT[pos * 32 + i];
    float s = sinT[pos * 32 + i];
    float2* p = (float2*)(t + (size_t)row * D_ + pair * 2);
    float2 v = *p;
    float2 o;
    o.x = v.x * c - v.y * s;
    o.y = v.x * s + v.y * c;
    *p = o;
}

// ---------------------------------------------------------------------------
// Tensor-core flash attention (split-bf16, x-part queries only).
// Mem-K RoPE fused into the K-tile load (positions 0..511).
// 64q x 64k tiles, HD=64. 256 threads, 8 warps (2q x 4n).
// ---------------------------------------------------------------------------
#define QST  72
#define QSTB (QST * 2)
#define PLANE (64 * QST * 2)
#define AOFF_QH 0
#define AOFF_QL (1 * PLANE)
#define AOFF_KH (2 * PLANE)
#define AOFF_KL (3 * PLANE)
#define AOFF_PH (4 * PLANE)
#define AOFF_PL (5 * PLANE)
#define AOFF_VH (6 * PLANE)
#define AOFF_VL (7 * PLANE)
#define AOFF_SS (8 * PLANE)
#define SST 66
#define AOFF_M  (AOFF_SS + 64 * SST * 4)
#define AOFF_L  (AOFF_M + 256)
#define AOFF_C  (AOFF_L + 256)
#define ATTN_SMEM2 (AOFF_C + 256)

__device__ __forceinline__ void split_store4(char* base, int elemOff, float4 v)
{
    __nv_bfloat16 h0 = __float2bfloat16(v.x);
    __nv_bfloat16 h1 = __float2bfloat16(v.y);
    __nv_bfloat16 h2 = __float2bfloat16(v.z);
    __nv_bfloat16 h3 = __float2bfloat16(v.w);
    __nv_bfloat162 hp0 = __halves2bfloat162(h0, h1);
    __nv_bfloat162 hp1 = __halves2bfloat162(h2, h3);
    __nv_bfloat162 lp0 = __floats2bfloat162_rn(v.x - __bfloat162float(h0),
                                               v.y - __bfloat162float(h1));
    __nv_bfloat162 lp1 = __floats2bfloat162_rn(v.z - __bfloat162float(h2),
                                               v.w - __bfloat162float(h3));
    *(uint2*)(base + elemOff * 2) = make_uint2(*(uint32_t*)&hp0, *(uint32_t*)&hp1);
    *(uint2*)(base + PLANE + elemOff * 2) = make_uint2(*(uint32_t*)&lp0, *(uint32_t*)&lp1);
}

__global__ __launch_bounds__(256, 2)
void attn_mma_kernel(const float* __restrict__ Qx,
                     const float* __restrict__ Km, const float* __restrict__ Vm,
                     const float* __restrict__ Kx, const float* __restrict__ Vx,
                     const float* __restrict__ cosT, const float* __restrict__ sinT,
                     float* __restrict__ Out, int sBase)
{
    extern __shared__ char sm[];
    float* Ss   = (float*)(sm + AOFF_SS);
    float* mrow = (float*)(sm + AOFF_M);
    float* lrow = (float*)(sm + AOFF_L);
    float* crow = (float*)(sm + AOFF_C);

    const int b  = blockIdx.z;
    const int h  = blockIdx.y;
    const int qt = blockIdx.x;
    const int tid = threadIdx.x;
    const int wid = tid >> 5, lane = tid & 31;
    const int wm = wid & 1, wn = wid >> 1;
    const int r  = lane >> 2, qc = (lane & 3) * 2;
    const int q0 = qt * 64;

    const uint32_t sbase = smem_u32(sm);
    const uint32_t aLaneOff = (uint32_t)((lane & 15) * QST + (lane >> 4) * 8) * 2;
    const uint32_t bLaneOff = (uint32_t)((((lane & 7) + ((lane >> 4) << 3)) * QST
                                          + ((lane >> 3) & 1) * 8) * 2);

    // --- Load Q tile (split to bf16 hi/lo) ---
    {
        const int j = tid >> 2, dq = (tid & 3) * 16;
        const float* Qp = &Qx[((size_t)(b * S_ + sBase + q0 + j)) * D_ + h * HD_ + dq];
        #pragma unroll
        for (int i = 0; i < 4; i++)
            split_store4(sm + AOFF_QH, j * QST + dq + i * 4, *(const float4*)(Qp + i * 4));
    }
    if (tid < 64) { mrow[tid] = -1e30f; lrow[tid] = 0.f; }

    float acc[2][2][4];
    #pragma unroll
    for (int i = 0; i < 2; i++)
        #pragma unroll
        for (int j = 0; j < 2; j++)
            #pragma unroll
            for (int e = 0; e < 4; e++) acc[i][j][e] = 0.f;
    __syncthreads();

    const int nkt = qt + 9;
    #pragma unroll 1
    for (int kt = 0; kt < nkt; kt++) {
        const float* Kp;
        const float* Vp;
        size_t rb;
        if (kt < 8) { Kp = Km; Vp = Vm; rb = (size_t)(b * M_ + kt * 64); }
        else        { Kp = Kx; Vp = Vx; rb = (size_t)(b * S_ + sBase + (kt - 8) * 64); }

        // K tile (mem part: rope fused, pos = kt*64 + j)
        {
            const int j = tid >> 2, dq = (tid & 3) * 16;
            const float* kp = &Kp[(rb + j) * D_ + h * HD_ + dq];
            if (kt < 8) {
                const int pos = kt * 64 + j;
                #pragma unroll
                for (int i = 0; i < 4; i++) {
                    float4 v = *(const float4*)(kp + i * 4);
                    int p0 = (dq + i * 4) >> 1;
                    float c0 = cosT[pos * 32 + p0],     s0 = sinT[pos * 32 + p0];
                    float c1 = cosT[pos * 32 + p0 + 1], s1 = sinT[pos * 32 + p0 + 1];
                    float4 rv;
                    rv.x = v.x * c0 - v.y * s0;
                    rv.y = v.x * s0 + v.y * c0;
                    rv.z = v.z * c1 - v.w * s1;
                    rv.w = v.z * s1 + v.w * c1;
                    split_store4(sm + AOFF_KH, j * QST + dq + i * 4, rv);
                }
            } else {
                #pragma unroll
                for (int i = 0; i < 4; i++)
                    split_store4(sm + AOFF_KH, j * QST + dq + i * 4, *(const float4*)(kp + i * 4));
            }
        }
        // V tile transposed: thread owns kpos=tid&63, 16 d -> Vt[d][kpos]
        {
            const int kp = tid & 63, db = (tid >> 6) * 16;
            const float* vp = &Vp[(rb + kp) * D_ + h * HD_ + db];
            #pragma unroll
            for (int i = 0; i < 4; i++) {
                float4 v = *(const float4*)(vp + i * 4);
                float vv[4] = {v.x, v.y, v.z, v.w};
                #pragma unroll
                for (int e = 0; e < 4; e++) {
                    int d = db + i * 4 + e;
                    __nv_bfloat16 hh = __float2bfloat16(vv[e]);
                    *(__nv_bfloat16*)(sm + AOFF_VH + (d * QST + kp) * 2) = hh;
                    *(__nv_bfloat16*)(sm + AOFF_VL + (d * QST + kp) * 2) =
                        __float2bfloat16(vv[e] - __bfloat162float(hh));
                }
            }
        }
        __syncthreads();

        // --- S = Q @ K^T (split, 4 k-steps over d) ---
        float s[2][2][4];
        #pragma unroll
        for (int i = 0; i < 2; i++)
            #pragma unroll
            for (int j = 0; j < 2; j++)
                #pragma unroll
                for (int e = 0; e < 4; e++) s[i][j][e] = 0.f;
        #pragma unroll
        for (int ks = 0; ks < 4; ks++) {
            const uint32_t kOff = ks * 32;
            uint32_t bh[4], bl[4];
            uint32_t baddr = sbase + AOFF_KH + (uint32_t)(wn * 16) * QSTB + kOff + bLaneOff;
            ldsm4(bh[0], bh[1], bh[2], bh[3], baddr);
            ldsm4(bl[0], bl[1], bl[2], bl[3], baddr + PLANE);
            #pragma unroll
            for (int mt = 0; mt < 2; mt++) {
                uint32_t aaddr = sbase + AOFF_QH + (uint32_t)(wm * 32 + mt * 16) * QSTB + kOff + aLaneOff;
                uint32_t ah0, ah1, ah2, ah3, al0, al1, al2, al3;
                ldsm4(ah0, ah1, ah2, ah3, aaddr);
                ldsm4(al0, al1, al2, al3, aaddr + PLANE);
                #pragma unroll
                for (int nt = 0; nt < 2; nt++) {
                    uint32_t b0 = bh[nt * 2], b1 = bh[nt * 2 + 1];
                    uint32_t c0 = bl[nt * 2], c1 = bl[nt * 2 + 1];
                    mma16816(s[mt][nt], ah0, ah1, ah2, ah3, b0, b1);
                    mma16816(s[mt][nt], ah0, ah1, ah2, ah3, c0, c1);
                    mma16816(s[mt][nt], al0, al1, al2, al3, b0, b1);
                }
            }
        }
        // scale + causal mask -> Ss
        #pragma unroll
        for (int mt = 0; mt < 2; mt++) {
            int row0 = wm * 32 + mt * 16 + r;
            int qi0 = M_ + q0 + row0, qi1 = qi0 + 8;
            #pragma unroll
            for (int nt = 0; nt < 2; nt++) {
                int col = wn * 16 + nt * 8 + qc;
                int kj = kt * 64 + col;
                Ss[row0 * SST + col]           = (kj     <= qi0) ? s[mt][nt][0] * 0.125f : -1e30f;
                Ss[row0 * SST + col + 1]       = (kj + 1 <= qi0) ? s[mt][nt][1] * 0.125f : -1e30f;
                Ss[(row0 + 8) * SST + col]     = (kj     <= qi1) ? s[mt][nt][2] * 0.125f : -1e30f;
                Ss[(row0 + 8) * SST + col + 1] = (kj + 1 <= qi1) ? s[mt][nt][3] * 0.125f : -1e30f;
            }
        }
        __syncthreads();

        // --- softmax: 4 threads per row ---
        {
            const int row = tid >> 2, part = tid & 3;
            float p[16];
            float mx = -1e30f;
            #pragma unroll
            for (int j = 0; j < 16; j++) {
                p[j] = Ss[row * SST + part * 16 + j];
                mx = fmaxf(mx, p[j]);
            }
            mx = fmaxf(mx, __shfl_xor_sync(0xffffffffu, mx, 1));
            mx = fmaxf(mx, __shfl_xor_sync(0xffffffffu, mx, 2));
            float mold = mrow[row];
            float mnew = fmaxf(mold, mx);
            float sum = 0.f;
            #pragma unroll
            for (int j = 0; j < 16; j++) {
                p[j] = __expf(p[j] - mnew);
                sum += p[j];
            }
            sum += __shfl_xor_sync(0xffffffffu, sum, 1);
            sum += __shfl_xor_sync(0xffffffffu, sum, 2);
            if (part == 0) {
                float c = __expf(mold - mnew);
                mrow[row] = mnew;
                lrow[row] = lrow[row] * c + sum;
                crow[row] = c;
            }
            #pragma unroll
            for (int j = 0; j < 8; j++) {
                float v0 = p[j * 2], v1 = p[j * 2 + 1];
                __nv_bfloat16 h0 = __float2bfloat16(v0);
                __nv_bfloat16 h1 = __float2bfloat16(v1);
                __nv_bfloat162 hp = __halves2bfloat162(h0, h1);
                __nv_bfloat162 lp = __floats2bfloat162_rn(v0 - __bfloat162float(h0),
                                                          v1 - __bfloat162float(h1));
                int off = (row * QST + part * 16 + j * 2) * 2;
                *(uint32_t*)(sm + AOFF_PH + off) = *(uint32_t*)&hp;
                *(uint32_t*)(sm + AOFF_PL + off) = *(uint32_t*)&lp;
            }
        }
        __syncthreads();

        // --- rescale acc, then O += P @ V ---
        #pragma unroll
        for (int mt = 0; mt < 2; mt++) {
            int row0 = wm * 32 + mt * 16 + r;
            float c0 = crow[row0], c1 = crow[row0 + 8];
            #pragma unroll
            for (int nt = 0; nt < 2; nt++) {
                acc[mt][nt][0] *= c0; acc[mt][nt][1] *= c0;
                acc[mt][nt][2] *= c1; acc[mt][nt][3] *= c1;
            }
        }
        #pragma unroll
        for (int ks = 0; ks < 4; ks++) {
            const uint32_t kOff = ks * 32;
            uint32_t bh[4], bl[4];
            uint32_t baddr = sbase + AOFF_VH + (uint32_t)(wn * 16) * QSTB + kOff + bLaneOff;
            ldsm4(bh[0], bh[1], bh[2], bh[3], baddr);
            ldsm4(bl[0], bl[1], bl[2], bl[3], baddr + PLANE);
            #pragma unroll
            for (int mt = 0; mt < 2; mt++) {
                uint32_t aaddr = sbase + AOFF_PH + (uint32_t)(wm * 32 + mt * 16) * QSTB + kOff + aLaneOff;
                uint32_t ph0, ph1, ph2, ph3, pl0, pl1, pl2, pl3;
                ldsm4(ph0, ph1, ph2, ph3, aaddr);
                ldsm4(pl0, pl1, pl2, pl3, aaddr + PLANE);
                #pragma unroll
                for (int nt = 0; nt < 2; nt++) {
                    uint32_t b0 = bh[nt * 2], b1 = bh[nt * 2 + 1];
                    uint32_t c0 = bl[nt * 2], c1 = bl[nt * 2 + 1];
                    mma16816(acc[mt][nt], ph0, ph1, ph2, ph3, b0, b1);
                    mma16816(acc[mt][nt], ph0, ph1, ph2, ph3, c0, c1);
                    mma16816(acc[mt][nt], pl0, pl1, pl2, pl3, b0, b1);
                }
            }
        }
        __syncthreads();
    }

    // --- epilogue ---
    #pragma unroll
    for (int mt = 0; mt < 2; mt++) {
        int row0 = wm * 32 + mt * 16 + r;
        float inv0 = 1.f / lrow[row0];
        float inv1 = 1.f / lrow[row0 + 8];
        int g0 = b * S_ + sBase + q0 + row0;
        #pragma unroll
        for (int nt = 0; nt < 2; nt++) {
            int col = wn * 16 + nt * 8 + qc;
            *(float2*)&Out[(size_t)g0 * D_ + h * HD_ + col] =
                make_float2(acc[mt][nt][0] * inv0, acc[mt][nt][1] * inv0);
            *(float2*)&Out[(size_t)(g0 + 8) * D_ + h * HD_ + col] =
                make_float2(acc[mt][nt][2] * inv1, acc[mt][nt][3] * inv1);
        }
    }
}

// ---------------------------------------------------------------------------
// Launch
// ---------------------------------------------------------------------------
extern "C" void kernel_launch(void* const* d_in, const int* in_sizes, int n_in,
                              void* d_out, int out_size)
{
    const float* x        = (const float*)d_in[0];
    const float* cosT     = (const float*)d_in[1];
    const float* sinT     = (const float*)d_in[2];
    const float* wq       = (const float*)d_in[3];
    const float* wk       = (const float*)d_in[4];
    const float* wv       = (const float*)d_in[5];
    const float* wo       = (const float*)d_in[6];
    const float* wm       = (const float*)d_in[7];
    const float* wkm      = (const float*)d_in[8];
    const float* wvm      = (const float*)d_in[9];
    const float* w1       = (const float*)d_in[10];
    const float* w3       = (const float*)d_in[11];
    const float* w2       = (const float*)d_in[12];
    const float* ffn_nw   = (const float*)d_in[13];
    const float* mem_nw   = (const float*)d_in[14];
    const float* omem     = (const float*)d_in[15];
    float* out = (float*)d_out;

    float *p_allout, *p_qx, *p_kx, *p_vx, *p_a, *p_hn, *p_t1, *p_t3, *p_m2, *p_k, *p_v;
    cudaGetSymbolAddress((void**)&p_allout, g_allout);
    cudaGetSymbolAddress((void**)&p_qx, g_qx);
    cudaGetSymbolAddress((void**)&p_kx, g_kx);
    cudaGetSymbolAddress((void**)&p_vx, g_vx);
    cudaGetSymbolAddress((void**)&p_a,  g_a);
    cudaGetSymbolAddress((void**)&p_hn, g_hn);
    cudaGetSymbolAddress((void**)&p_t1, g_t1);
    cudaGetSymbolAddress((void**)&p_t3, g_t3);
    cudaGetSymbolAddress((void**)&p_m2, g_m2);
    cudaGetSymbolAddress((void**)&p_k,  g_k);
    cudaGetSymbolAddress((void**)&p_v,  g_v);

    cudaFuncSetAttribute(attn_mma_kernel,
                         cudaFuncAttributeMaxDynamicSharedMemorySize, ATTN_SMEM2);
    cudaFuncSetAttribute(mma_gemm_kernel<128, 128, false>,
                         cudaFuncAttributeMaxDynamicSharedMemorySize, SMEM_OF(128, 128));
    cudaFuncSetAttribute(mma_gemm_kernel<64, 64, false>,
                         cudaFuncAttributeMaxDynamicSharedMemorySize, SMEM_OF(64, 64));
    cudaFuncSetAttribute(mma_gemm_kernel<64, 128, false>,
                         cudaFuncAttributeMaxDynamicSharedMemorySize, SMEM_OF(64, 128));
    cudaFuncSetAttribute(mma_gemm_kernel<64, 64, true>,
                         cudaFuncAttributeMaxDynamicSharedMemorySize, SMEM_OF(64, 64));

    const long long MD  = (long long)M_ * D_;
    const long long MH  = (long long)M_ * HID_;
    const long long SD  = (long long)S_ * D_;

    // ---- Upfront: all-step QKV projections + RoPE ----
    mma_gemm_kernel<128, 128, false><<<dim3(24, 32, 2), 256, SMEM_OF(128, 128)>>>(
        x, SD, wq, wk, wv, p_qx, p_kx, p_vx, SD, SD, SD, D_, D_, 8);
    {
        int n = B_ * S_ * (D_ / 2);
        rope_kernel<<<(n + 255) / 256, 256>>>(p_qx, cosT, sinT, 512, M_, n);
        rope_kernel<<<(n + 255) / 256, 256>>>(p_kx, cosT, sinT, 512, M_, n);
    }

    // ---- Sequential memory chain ----
    for (int s = 0; s < NSTEP; s++) {
        const float* om = (s == 0) ? omem : (p_allout + (size_t)(s - 1) * M_ * D_);
        const long long omB = (s == 0) ? 0LL : SD;

        mma_gemm_kernel<64, 64, false><<<dim3(16, 8, 2), 256, SMEM_OF(64, 64)>>>(
            om, omB, wm, wm, wm, p_a, p_a, p_a, MD, MD, MD, D_, D_, 16);
        rmsnorm_kernel<<<B_ * M_, 256>>>(p_a, ffn_nw, p_hn);
        mma_gemm_kernel<64, 128, false><<<dim3(44, 8, 2), 256, SMEM_OF(64, 128)>>>(
            p_hn, MD, w1, w3, w3, p_t1, p_t3, p_t3, MH, MH, MH, D_, HID_, 22);
        silu_gate_kernel<<<(B_ * M_ * HID_ / 4 + 255) / 256, 256>>>(
            (float4*)p_t1, (const float4*)p_t3, B_ * M_ * HID_ / 4);
        mma_gemm_kernel<64, 64, true><<<dim3(16, 8, 2), 256, SMEM_OF(64, 64)>>>(
            p_t1, MH, w2, w2, w2, p_a, p_a, p_a, MD, MD, MD, HID_, D_, 16);
        rmsnorm_kernel<<<B_ * M_, 256>>>(p_a, mem_nw, p_m2);
        mma_gemm_kernel<64, 128, false><<<dim3(16, 8, 2), 256, SMEM_OF(64, 128)>>>(
            p_m2, MD, wkm, wvm, wvm, p_k, p_v, p_v, MD, MD, MD, D_, D_, 8);
        // (mem-K rope fused into attention)
        attn_mma_kernel<<<dim3(M_ / 64, H_, B_), 256, ATTN_SMEM2>>>(
            p_qx, p_k, p_v, p_kx, p_vx, cosT, sinT, p_allout, s * M_);
    }

    // out = allout @ wo
    mma_gemm_kernel<128, 128, false><<<dim3(8, 64, 1), 256, SMEM_OF(128, 128)>>>(
        p_allout, 0LL, wo, wo, wo, out, out, out, 0LL, 0LL, 0LL, D_, D_, 8);
}